// round 1
// baseline (speedup 1.0000x reference)
#include <cuda_runtime.h>
#include <cuda_bf16.h>

#define NN   50000
#define NE   800000
#define FIN  128
#define HID  72
#define HG   18      // HID/4
#define NLAY 3

// ---------------- scratch (static __device__, no allocations) ----------------
__device__ int   g_degi[NN];
__device__ float g_dinv[NN];
__device__ float g_norm[NE];
__device__ int   g_off[NN + 1];
__device__ int   g_cur[NN];
__device__ int   g_erow[NE];
__device__ float g_enrm[NE];
__device__ float g_h[NN * HID];
__device__ float g_m[NN * HID];     // also U in final stage
__device__ float g_agg[NN * HID];   // also V in final stage
__device__ float g_stats[2 * HID];  // zero-init; re-zeroed by k_bn_final
__device__ float g_scale[HID];
__device__ float g_shift[HID];
__device__ float g_C[160 * HID];    // folded weights: [0:72)=C1, [72:144)=C2, [144:160)=C3
__device__ float g_bz[HID];

// ---------------- helpers ----------------
__device__ __forceinline__ void fma4(float4& a, float s, const float4& b) {
    a.x = __fmaf_rn(s, b.x, a.x);
    a.y = __fmaf_rn(s, b.y, a.y);
    a.z = __fmaf_rn(s, b.z, a.z);
    a.w = __fmaf_rn(s, b.w, a.w);
}
__device__ __forceinline__ float tanh_fast(float x) {
    // tanh(x) = 1 - 2/(e^{2x}+1); __expf accurate to ~2 ulp -> ~1e-7 rel err
    float e = __expf(2.0f * x);
    return 1.0f - __fdividef(2.0f, e + 1.0f);
}

// ---------------- graph preprocessing ----------------
__global__ void k_zero_deg() {
    int i = blockIdx.x * blockDim.x + threadIdx.x;
    if (i < NN) g_degi[i] = 0;
}
__global__ void k_deg(const int* __restrict__ col) {
    int e = blockIdx.x * blockDim.x + threadIdx.x;
    if (e < NE) atomicAdd(&g_degi[col[e]], 1);
}
__global__ void k_dinv() {
    int i = blockIdx.x * blockDim.x + threadIdx.x;
    if (i < NN) {
        int d = g_degi[i];
        g_dinv[i] = (d > 0) ? rsqrtf((float)d) : 0.0f;
    }
}
__global__ void k_norm(const int* __restrict__ row, const int* __restrict__ col) {
    int e = blockIdx.x * blockDim.x + threadIdx.x;
    if (e < NE) g_norm[e] = g_dinv[row[e]] * g_dinv[col[e]];
}
// single-block exclusive scan of in-degrees -> CSR offsets + cursor copy
__global__ void k_scan() {
    __shared__ int sp[1024];
    int tid = threadIdx.x;
    const int CH = (NN + 1023) / 1024;  // 49
    int start = tid * CH;
    int end = min(start + CH, NN);
    int loc = 0;
    for (int i = start; i < end; i++) loc += g_degi[i];
    sp[tid] = loc;
    __syncthreads();
    for (int off = 1; off < 1024; off <<= 1) {
        int v = (tid >= off) ? sp[tid - off] : 0;
        __syncthreads();
        sp[tid] += v;
        __syncthreads();
    }
    int run = sp[tid] - loc;  // exclusive prefix
    for (int i = start; i < end; i++) {
        g_off[i] = run;
        g_cur[i] = run;
        run += g_degi[i];
    }
    if (tid == 1023) g_off[NN] = NE;
}
__global__ void k_sort(const int* __restrict__ row, const int* __restrict__ col) {
    int e = blockIdx.x * blockDim.x + threadIdx.x;
    if (e < NE) {
        int c = col[e];
        int p = atomicAdd(&g_cur[c], 1);
        g_erow[p] = row[e];
        g_enrm[p] = g_norm[e];
    }
}

// ---------------- node GEMMs ----------------
// h = relu(x @ W + b), x:[NN,128], W:[128,72]. block (18,16), 16 nodes/block.
__global__ void __launch_bounds__(288) k_node_lin(const float* __restrict__ x,
                                                  const float* __restrict__ W,
                                                  const float* __restrict__ b) {
    __shared__ float4 sW[FIN * HG];
    __shared__ float sx[16 * 132];  // stride 132 (banks ok, float4-stageable)
    int tx = threadIdx.x, ty = threadIdx.y, tid = ty * 18 + tx;
    const float4* W4 = (const float4*)W;
    for (int i = tid; i < FIN * HG; i += 288) sW[i] = W4[i];
    int n0 = blockIdx.x * 16;
    const float4* x4 = (const float4*)x;
    float4* sx4 = (float4*)sx;
    for (int i = tid; i < 16 * 32; i += 288) {
        int r = i >> 5, kq = i & 31;
        int n = n0 + r;
        float4 v = make_float4(0.f, 0.f, 0.f, 0.f);
        if (n < NN) v = x4[n * 32 + kq];
        sx4[r * 33 + kq] = v;
    }
    __syncthreads();
    int n = n0 + ty;
    float4 acc = __ldg(&((const float4*)b)[tx]);
    const float* xr = &sx[ty * 132];
#pragma unroll 8
    for (int k = 0; k < FIN; k++) {
        float xv = xr[k];
        float4 w = sW[k * HG + tx];
        fma4(acc, xv, w);
    }
    if (n < NN) {
        acc.x = fmaxf(acc.x, 0.f); acc.y = fmaxf(acc.y, 0.f);
        acc.z = fmaxf(acc.z, 0.f); acc.w = fmaxf(acc.w, 0.f);
        ((float4*)g_h)[n * HG + tx] = acc;
    }
}

// outA = g_h @ Wa ; outB = g_h @ Wb (+bias). Writes g_m / g_agg.
__global__ void __launch_bounds__(288) k_dualgemm(const float* __restrict__ Wa,
                                                  const float* __restrict__ Wb,
                                                  const float* __restrict__ bias) {
    __shared__ float4 sA[HID * HG], sB[HID * HG];
    __shared__ float sx[16 * 76];
    int tx = threadIdx.x, ty = threadIdx.y, tid = ty * 18 + tx;
    const float4* Wa4 = (const float4*)Wa;
    const float4* Wb4 = (const float4*)Wb;
    for (int i = tid; i < HID * HG; i += 288) {
        sA[i] = Wa4[i];
        sB[i] = Wb4[i];
    }
    int n0 = blockIdx.x * 16;
    const float4* h4 = (const float4*)g_h;
    float4* sx4 = (float4*)sx;
    for (int i = tid; i < 16 * HG; i += 288) {
        int r = i / HG, kq = i % HG;
        int n = n0 + r;
        float4 v = make_float4(0.f, 0.f, 0.f, 0.f);
        if (n < NN) v = h4[n * HG + kq];
        sx4[r * 19 + kq] = v;
    }
    __syncthreads();
    int n = n0 + ty;
    float4 aM = make_float4(0.f, 0.f, 0.f, 0.f);
    float4 aB = bias ? __ldg(&((const float4*)bias)[tx]) : make_float4(0.f, 0.f, 0.f, 0.f);
    const float* xr = &sx[ty * 76];
#pragma unroll 8
    for (int k = 0; k < HID; k++) {
        float xv = xr[k];
        fma4(aM, xv, sA[k * HG + tx]);
        fma4(aB, xv, sB[k * HG + tx]);
    }
    if (n < NN) {
        ((float4*)g_m)[n * HG + tx] = aM;
        ((float4*)g_agg)[n * HG + tx] = aB;
    }
}

// gather-side aggregation: g_agg[n] += sum_{edges into n} norm * g_m[src]
__global__ void __launch_bounds__(288) k_aggregate() {
    int tx = threadIdx.x, ty = threadIdx.y;
    int n = blockIdx.x * 16 + ty;
    if (n >= NN) return;
    int s = g_off[n], e = g_off[n + 1];
    const float4* m4 = (const float4*)g_m;
    float4* agg4 = (float4*)g_agg;
    float4 acc = agg4[n * HG + tx];
    for (int j = s; j < e; j++) {
        int r = __ldg(&g_erow[j]);
        float w = __ldg(&g_enrm[j]);
        float4 mv = __ldg(&m4[r * HG + tx]);
        fma4(acc, w, mv);
    }
    agg4[n * HG + tx] = acc;
}

// h = relu(agg); accumulate per-channel sum/sumsq. block (72,4)
__global__ void k_relu_stats() {
    int tx = threadIdx.x;
    int ty = threadIdx.y;
    float s = 0.f, ss = 0.f;
    for (int n = blockIdx.x * 4 + ty; n < NN; n += gridDim.x * 4) {
        float v = g_agg[n * HID + tx];
        v = fmaxf(v, 0.f);
        g_h[n * HID + tx] = v;
        s += v;
        ss += v * v;
    }
    __shared__ float rs[4][HID], rq[4][HID];
    rs[ty][tx] = s;
    rq[ty][tx] = ss;
    __syncthreads();
    if (ty == 0) {
        float S = rs[0][tx] + rs[1][tx] + rs[2][tx] + rs[3][tx];
        float Q = rq[0][tx] + rq[1][tx] + rq[2][tx] + rq[3][tx];
        atomicAdd(&g_stats[tx], S);
        atomicAdd(&g_stats[HID + tx], Q);
    }
}

__global__ void k_bn_final(const float* __restrict__ gamma, const float* __restrict__ beta) {
    int t = threadIdx.x;
    float S = g_stats[t], Q = g_stats[HID + t];
    float mu = S * (1.0f / NN);
    float var = Q * (1.0f / NN) - mu * mu;
    float sc = __ldg(&gamma[t]) * rsqrtf(var + 1e-5f);
    g_scale[t] = sc;
    g_shift[t] = __ldg(&beta[t]) - mu * sc;
    g_stats[t] = 0.f;         // re-zero for next use (deterministic across replays)
    g_stats[HID + t] = 0.f;
}

__global__ void k_bn_apply() {
    int idx = blockIdx.x * blockDim.x + threadIdx.x;
    if (idx >= NN * HG) return;
    float4 v = ((const float4*)g_h)[idx];
    int chg = idx % HG;
    float4 sc = __ldg(&((const float4*)g_scale)[chg]);
    float4 sh = __ldg(&((const float4*)g_shift)[chg]);
    v.x = __fmaf_rn(v.x, sc.x, sh.x);
    v.y = __fmaf_rn(v.y, sc.y, sh.y);
    v.z = __fmaf_rn(v.z, sc.z, sh.z);
    v.w = __fmaf_rn(v.w, sc.w, sh.w);
    ((float4*)g_h)[idx] = v;
}

// fold edge-MLP front-end: C[160][72], bz[72]
// C rows 0..143 = W1(144x72) @ M1top(72x72); rows 144..159 = W2(16x72) @ M1bot(72x72)
__global__ void __launch_bounds__(288) k_fold(const float* __restrict__ W1,
                                              const float* __restrict__ W2,
                                              const float* __restrict__ M1,
                                              const float* __restrict__ b1,
                                              const float* __restrict__ b2,
                                              const float* __restrict__ bm) {
    __shared__ float4 sM1[144 * HG];
    int tid = threadIdx.x;
    const float4* M1_4 = (const float4*)M1;
    for (int i = tid; i < 144 * HG; i += 288) sM1[i] = M1_4[i];
    __syncthreads();
    int rowi = blockIdx.x * 16 + tid / HG;
    int chg = tid % HG;
    if (rowi < 160) {
        float4 acc = make_float4(0.f, 0.f, 0.f, 0.f);
        if (rowi < 144) {
#pragma unroll 8
            for (int k = 0; k < HID; k++)
                fma4(acc, __ldg(&W1[rowi * HID + k]), sM1[k * HG + chg]);
        } else {
            int r2 = rowi - 144;
#pragma unroll
            for (int k = 0; k < HID; k++)
                fma4(acc, __ldg(&W2[r2 * HID + k]), sM1[(HID + k) * HG + chg]);
        }
        ((float4*)g_C)[rowi * HG + chg] = acc;
    }
    if (blockIdx.x == 0 && tid < HG) {
        float4 acc = __ldg(&((const float4*)bm)[tid]);
#pragma unroll 8
        for (int k = 0; k < HID; k++) {
            fma4(acc, __ldg(&b1[k]), sM1[k * HG + tid]);
            fma4(acc, __ldg(&b2[k]), sM1[(HID + k) * HG + tid]);
        }
        ((float4*)g_bz)[tid] = acc;
    }
}

// final per-edge stage: z = U[r] + V[c] + attr@C3 + bz; out = tanh(z).w2 + b2m
__global__ void k_edge(const int* __restrict__ row, const int* __restrict__ col,
                       const float* __restrict__ attr, const float* __restrict__ w2,
                       const float* __restrict__ b2m, float* __restrict__ out) {
    __shared__ float sh_part[288];
    int tid = threadIdx.x;
    int el = tid / HG;          // 0..15 edge-in-tile
    int chg = tid - el * HG;    // 0..17 channel group
    const float4* C3_4 = (const float4*)(g_C + 144 * HID);
    float4 c3[16];
#pragma unroll
    for (int k = 0; k < 16; k++) c3[k] = __ldg(&C3_4[k * HG + chg]);
    float4 bz = __ldg(&((const float4*)g_bz)[chg]);
    float4 wv = __ldg(&((const float4*)w2)[chg]);
    float bout = __ldg(b2m);
    const float4* U4 = (const float4*)g_m;
    const float4* V4 = (const float4*)g_agg;
    const float4* a4 = (const float4*)attr;
    const int ntiles = NE / 16;
    for (int tile = blockIdx.x; tile < ntiles; tile += gridDim.x) {
        int e = tile * 16 + el;
        int r = __ldg(&row[e]);
        int c = __ldg(&col[e]);
        float4 u = __ldg(&U4[r * HG + chg]);
        float4 v = __ldg(&V4[c * HG + chg]);
        float4 z;
        z.x = u.x + v.x + bz.x;
        z.y = u.y + v.y + bz.y;
        z.z = u.z + v.z + bz.z;
        z.w = u.w + v.w + bz.w;
        float4 a0 = __ldg(&a4[e * 4 + 0]);
        float4 a1 = __ldg(&a4[e * 4 + 1]);
        float4 a2 = __ldg(&a4[e * 4 + 2]);
        float4 a3 = __ldg(&a4[e * 4 + 3]);
        fma4(z, a0.x, c3[0]);  fma4(z, a0.y, c3[1]);  fma4(z, a0.z, c3[2]);  fma4(z, a0.w, c3[3]);
        fma4(z, a1.x, c3[4]);  fma4(z, a1.y, c3[5]);  fma4(z, a1.z, c3[6]);  fma4(z, a1.w, c3[7]);
        fma4(z, a2.x, c3[8]);  fma4(z, a2.y, c3[9]);  fma4(z, a2.z, c3[10]); fma4(z, a2.w, c3[11]);
        fma4(z, a3.x, c3[12]); fma4(z, a3.y, c3[13]); fma4(z, a3.z, c3[14]); fma4(z, a3.w, c3[15]);
        float p = tanh_fast(z.x) * wv.x + tanh_fast(z.y) * wv.y +
                  tanh_fast(z.z) * wv.z + tanh_fast(z.w) * wv.w;
        sh_part[tid] = p;
        __syncthreads();
        if (tid < 16) {
            float ssum = 0.f;
#pragma unroll
            for (int j = 0; j < HG; j++) ssum += sh_part[tid * HG + j];
            out[tile * 16 + tid] = ssum + bout;
        }
        __syncthreads();
    }
}

// ---------------- launch ----------------
extern "C" void kernel_launch(void* const* d_in, const int* in_sizes, int n_in,
                              void* d_out, int out_size) {
    const float* x     = (const float*)d_in[0];
    const int*   ei    = (const int*)d_in[1];
    const float* attr  = (const float*)d_in[2];
    const float* nlw   = (const float*)d_in[3];
    const float* nlb   = (const float*)d_in[4];
    const float* convw = (const float*)d_in[5];
    const float* convv = (const float*)d_in[6];
    const float* convb = (const float*)d_in[7];
    const float* gamma = (const float*)d_in[8];
    const float* beta  = (const float*)d_in[9];
    const float* W1    = (const float*)d_in[10];
    const float* b1    = (const float*)d_in[11];
    const float* W2    = (const float*)d_in[12];
    const float* b2e   = (const float*)d_in[13];
    const float* M1    = (const float*)d_in[14];
    const float* bm    = (const float*)d_in[15];
    const float* w2    = (const float*)d_in[16];
    const float* b2m   = (const float*)d_in[17];
    const int* row = ei;
    const int* col = ei + NE;
    float* out = (float*)d_out;

    float* pC = nullptr;
    cudaGetSymbolAddress((void**)&pC, g_C);

    dim3 blk(18, 16);
    const int GN = (NN + 15) / 16;  // 3125

    k_zero_deg<<<(NN + 255) / 256, 256>>>();
    k_deg<<<(NE + 255) / 256, 256>>>(col);
    k_dinv<<<(NN + 255) / 256, 256>>>();
    k_norm<<<(NE + 255) / 256, 256>>>(row, col);
    k_scan<<<1, 1024>>>();
    k_sort<<<(NE + 255) / 256, 256>>>(row, col);

    k_node_lin<<<GN, blk>>>(x, nlw, nlb);
    for (int t = 0; t < NLAY; t++) {
        k_dualgemm<<<GN, blk>>>(convw + t * HID * HID, convv + t * HID * HID, convb + t * HID);
        k_aggregate<<<GN, blk>>>();
        k_relu_stats<<<256, dim3(HID, 4)>>>();
        k_bn_final<<<1, HID>>>(gamma + t * HID, beta + t * HID);
        k_bn_apply<<<(NN * HG + 255) / 256, 256>>>();
    }
    k_fold<<<10, 288>>>(W1, W2, M1, b1, b2e, bm);
    k_dualgemm<<<GN, blk>>>(pC, pC + HID * HID, nullptr);  // U = h@C1, V = h@C2
    k_edge<<<3700, 288>>>(row, col, attr, w2, b2m, out);
}

// round 2
// speedup vs baseline: 1.4097x; 1.4097x over previous
#include <cuda_runtime.h>

#define NN   50000
#define NE   800000
#define FIN  128
#define HID  72
#define HG   18      // HID/4
#define NLAY 3

// ---------------- scratch (static __device__, no allocations) ----------------
__device__ int   g_degi[NN];
__device__ float g_dinv[NN];
__device__ int   g_off[NN + 1];
__device__ int   g_cur[NN];
__device__ int2  g_edge[NE];        // {src row, __float_as_int(norm)} CSR-by-col
__device__ float g_h[NN * HID];
__device__ float g_m[NN * HID];     // also U in final stage
__device__ float g_agg[NN * HID];   // also V in final stage
__device__ float g_stats[2 * HID];  // zeroed at init; re-zeroed by k_bn_final
__device__ float g_scale[HID];
__device__ float g_shift[HID];
__device__ float g_C[160 * HID];    // folded weights
__device__ float g_bz[HID];

// ---------------- helpers ----------------
__device__ __forceinline__ void fma4(float4& a, float s, const float4& b) {
    a.x = __fmaf_rn(s, b.x, a.x);
    a.y = __fmaf_rn(s, b.y, a.y);
    a.z = __fmaf_rn(s, b.z, a.z);
    a.w = __fmaf_rn(s, b.w, a.w);
}
__device__ __forceinline__ float tanh_fast(float x) {
    float e = __expf(2.0f * x);
    return 1.0f - __fdividef(2.0f, e + 1.0f);
}

// ---------------- graph preprocessing ----------------
__global__ void k_zero_deg() {
    int i = blockIdx.x * blockDim.x + threadIdx.x;
    if (i < NN) g_degi[i] = 0;
}
__global__ void k_deg(const int* __restrict__ col) {
    int e = blockIdx.x * blockDim.x + threadIdx.x;
    if (e < NE) atomicAdd(&g_degi[col[e]], 1);
}
// single-block exclusive scan of in-degrees -> CSR offsets + cursors + dinv
__global__ void k_scan() {
    __shared__ int sp[1024];
    int tid = threadIdx.x;
    const int CH = (NN + 1023) / 1024;  // 49
    int start = tid * CH;
    int end = min(start + CH, NN);
    int loc = 0;
    for (int i = start; i < end; i++) loc += g_degi[i];
    sp[tid] = loc;
    __syncthreads();
    for (int off = 1; off < 1024; off <<= 1) {
        int v = (tid >= off) ? sp[tid - off] : 0;
        __syncthreads();
        sp[tid] += v;
        __syncthreads();
    }
    int run = sp[tid] - loc;  // exclusive prefix
    for (int i = start; i < end; i++) {
        int d = g_degi[i];
        g_off[i] = run;
        g_cur[i] = run;
        run += d;
        g_dinv[i] = (d > 0) ? rsqrtf((float)d) : 0.0f;
    }
    if (tid == 1023) g_off[NN] = NE;
}
__global__ void k_sort(const int* __restrict__ row, const int* __restrict__ col) {
    int e = blockIdx.x * blockDim.x + threadIdx.x;
    if (e < NE) {
        int r = row[e], c = col[e];
        float nrm = g_dinv[r] * g_dinv[c];
        int p = atomicAdd(&g_cur[c], 1);
        g_edge[p] = make_int2(r, __float_as_int(nrm));
    }
}

// ---------------- node GEMMs (register-blocked, 64 nodes / block) ----------------
// h = relu(x @ W + b). Block 288 = 18 tx (output f4) x 16 ty, 4 nodes/thread.
// K=128 staged in 4 chunks of 32 to stay under 48KB static smem.
__global__ void __launch_bounds__(288) k_node_lin(const float* __restrict__ x,
                                                  const float* __restrict__ W,
                                                  const float* __restrict__ b) {
    __shared__ float4 sW[32 * HG];   // 9216B: W chunk [32][18]
    __shared__ float4 sx[64 * 9];    // 9216B: x chunk [64 nodes][8 f4], stride 9
    int tid = threadIdx.x;
    int tx = tid % HG, ty = tid / HG;     // ty 0..15
    int n0 = blockIdx.x * 64;
    const float4* W4 = (const float4*)W;
    const float4* x4 = (const float4*)x;
    float4 acc[4];
    float4 bb = __ldg(&((const float4*)b)[tx]);
#pragma unroll
    for (int i = 0; i < 4; i++) acc[i] = bb;

    for (int c = 0; c < 4; c++) {
        __syncthreads();
        for (int i = tid; i < 32 * HG; i += 288) {
            int kk = i / HG, j = i % HG;
            sW[i] = W4[(c * 32 + kk) * HG + j];
        }
        for (int i = tid; i < 64 * 8; i += 288) {
            int r = i >> 3, kq = i & 7;
            int n = n0 + r;
            float4 v = make_float4(0.f, 0.f, 0.f, 0.f);
            if (n < NN) v = x4[n * 32 + c * 8 + kq];
            sx[r * 9 + kq] = v;
        }
        __syncthreads();
        const float* sxf = (const float*)sx;
#pragma unroll 8
        for (int k = 0; k < 32; k++) {
            float4 w = sW[k * HG + tx];
#pragma unroll
            for (int i = 0; i < 4; i++)
                fma4(acc[i], sxf[(ty * 4 + i) * 36 + k], w);
        }
    }
#pragma unroll
    for (int i = 0; i < 4; i++) {
        int n = n0 + ty * 4 + i;
        if (n < NN) {
            float4 a = acc[i];
            a.x = fmaxf(a.x, 0.f); a.y = fmaxf(a.y, 0.f);
            a.z = fmaxf(a.z, 0.f); a.w = fmaxf(a.w, 0.f);
            ((float4*)g_h)[n * HG + tx] = a;
        }
    }
}

// [g_m | g_agg] = (bn(h)) @ [Wa | Wb] (+bias on Wb half).
// Block 288 = 36 tx (output f4 over concatenated 144 cols) x 8 ty, 8 nodes/thread.
// K=72 staged in 2 chunks of 36.
__global__ void __launch_bounds__(288) k_dualgemm(const float* __restrict__ Wa,
                                                  const float* __restrict__ Wb,
                                                  const float* __restrict__ bias,
                                                  const float* __restrict__ scale,
                                                  const float* __restrict__ shift) {
    __shared__ float4 sW[36 * 36];   // 20736B
    __shared__ float4 sx[64 * 10];   // 10240B: [64 nodes][9 f4], stride 10
    int tid = threadIdx.x;
    int tx = tid % 36, ty = tid / 36;   // ty 0..7
    int n0 = blockIdx.x * 64;
    const float4* Wa4 = (const float4*)Wa;
    const float4* Wb4 = (const float4*)Wb;
    const float4* h4 = (const float4*)g_h;
    float4 acc[8];
    float4 binit = make_float4(0.f, 0.f, 0.f, 0.f);
    if (bias != nullptr && tx >= HG) binit = __ldg(&((const float4*)bias)[tx - HG]);
#pragma unroll
    for (int i = 0; i < 8; i++) acc[i] = binit;

    for (int c = 0; c < 2; c++) {
        __syncthreads();
        for (int i = tid; i < 36 * 36; i += 288) {
            int kk = i / 36, j = i % 36;
            sW[i] = (j < HG) ? Wa4[(c * 36 + kk) * HG + j]
                             : Wb4[(c * 36 + kk) * HG + j - HG];
        }
        if (scale != nullptr) {
            for (int i = tid; i < 64 * 9; i += 288) {
                int r = i / 9, kq = i % 9;
                int n = n0 + r;
                float4 v = make_float4(0.f, 0.f, 0.f, 0.f);
                if (n < NN) {
                    v = h4[n * HG + c * 9 + kq];
                    float4 sc = __ldg(&((const float4*)scale)[c * 9 + kq]);
                    float4 sh = __ldg(&((const float4*)shift)[c * 9 + kq]);
                    v.x = __fmaf_rn(v.x, sc.x, sh.x);
                    v.y = __fmaf_rn(v.y, sc.y, sh.y);
                    v.z = __fmaf_rn(v.z, sc.z, sh.z);
                    v.w = __fmaf_rn(v.w, sc.w, sh.w);
                }
                sx[r * 10 + kq] = v;
            }
        } else {
            for (int i = tid; i < 64 * 9; i += 288) {
                int r = i / 9, kq = i % 9;
                int n = n0 + r;
                float4 v = make_float4(0.f, 0.f, 0.f, 0.f);
                if (n < NN) v = h4[n * HG + c * 9 + kq];
                sx[r * 10 + kq] = v;
            }
        }
        __syncthreads();
        const float* sxf = (const float*)sx;
#pragma unroll 4
        for (int k = 0; k < 36; k++) {
            float4 w = sW[k * 36 + tx];
#pragma unroll
            for (int i = 0; i < 8; i++)
                fma4(acc[i], sxf[(ty * 8 + i) * 40 + k], w);
        }
    }
    float4* m4 = (float4*)g_m;
    float4* agg4 = (float4*)g_agg;
#pragma unroll
    for (int i = 0; i < 8; i++) {
        int n = n0 + ty * 8 + i;
        if (n < NN) {
            if (tx < HG) m4[n * HG + tx] = acc[i];
            else         agg4[n * HG + tx - HG] = acc[i];
        }
    }
}

// gather aggregation + relu + BN-stats fused. Block (18,16), 16 nodes/block.
__global__ void __launch_bounds__(288) k_aggregate() {
    int tx = threadIdx.x, ty = threadIdx.y;
    int n = blockIdx.x * 16 + ty;     // NN = 3125*16 exact
    int s = g_off[n], e = g_off[n + 1];
    const float4* m4 = (const float4*)g_m;
    float4 acc = ((const float4*)g_agg)[n * HG + tx];
    int j = s;
    for (; j + 1 < e; j += 2) {
        int2 e0 = __ldg(&g_edge[j]);
        int2 e1 = __ldg(&g_edge[j + 1]);
        float4 v0 = __ldg(&m4[e0.x * HG + tx]);
        float4 v1 = __ldg(&m4[e1.x * HG + tx]);
        fma4(acc, __int_as_float(e0.y), v0);
        fma4(acc, __int_as_float(e1.y), v1);
    }
    if (j < e) {
        int2 e0 = __ldg(&g_edge[j]);
        fma4(acc, __int_as_float(e0.y), __ldg(&m4[e0.x * HG + tx]));
    }
    acc.x = fmaxf(acc.x, 0.f); acc.y = fmaxf(acc.y, 0.f);
    acc.z = fmaxf(acc.z, 0.f); acc.w = fmaxf(acc.w, 0.f);
    ((float4*)g_h)[n * HG + tx] = acc;

    __shared__ float4 red[2][16][19];
    float4 sq;
    sq.x = acc.x * acc.x; sq.y = acc.y * acc.y;
    sq.z = acc.z * acc.z; sq.w = acc.w * acc.w;
    red[0][ty][tx] = acc;
    red[1][ty][tx] = sq;
    __syncthreads();
    if (ty == 0) {
        float4 S = make_float4(0.f, 0.f, 0.f, 0.f);
        float4 Q = make_float4(0.f, 0.f, 0.f, 0.f);
#pragma unroll
        for (int r = 0; r < 16; r++) {
            float4 a = red[0][r][tx], q = red[1][r][tx];
            S.x += a.x; S.y += a.y; S.z += a.z; S.w += a.w;
            Q.x += q.x; Q.y += q.y; Q.z += q.z; Q.w += q.w;
        }
        atomicAdd(&g_stats[tx * 4 + 0], S.x);
        atomicAdd(&g_stats[tx * 4 + 1], S.y);
        atomicAdd(&g_stats[tx * 4 + 2], S.z);
        atomicAdd(&g_stats[tx * 4 + 3], S.w);
        atomicAdd(&g_stats[HID + tx * 4 + 0], Q.x);
        atomicAdd(&g_stats[HID + tx * 4 + 1], Q.y);
        atomicAdd(&g_stats[HID + tx * 4 + 2], Q.z);
        atomicAdd(&g_stats[HID + tx * 4 + 3], Q.w);
    }
}

__global__ void k_bn_final(const float* __restrict__ gamma, const float* __restrict__ beta) {
    int t = threadIdx.x;
    float S = g_stats[t], Q = g_stats[HID + t];
    float mu = S * (1.0f / NN);
    float var = Q * (1.0f / NN) - mu * mu;
    float sc = __ldg(&gamma[t]) * rsqrtf(var + 1e-5f);
    g_scale[t] = sc;
    g_shift[t] = __ldg(&beta[t]) - mu * sc;
    g_stats[t] = 0.f;
    g_stats[HID + t] = 0.f;
}

// fold edge-MLP front-end: C[160][72], bz[72]
__global__ void __launch_bounds__(288) k_fold(const float* __restrict__ W1,
                                              const float* __restrict__ W2,
                                              const float* __restrict__ M1,
                                              const float* __restrict__ b1,
                                              const float* __restrict__ b2,
                                              const float* __restrict__ bm) {
    __shared__ float4 sM1[144 * HG];
    int tid = threadIdx.x;
    const float4* M1_4 = (const float4*)M1;
    for (int i = tid; i < 144 * HG; i += 288) sM1[i] = M1_4[i];
    __syncthreads();
    int rowi = blockIdx.x * 16 + tid / HG;
    int chg = tid % HG;
    if (rowi < 160) {
        float4 acc = make_float4(0.f, 0.f, 0.f, 0.f);
        if (rowi < 144) {
#pragma unroll 8
            for (int k = 0; k < HID; k++)
                fma4(acc, __ldg(&W1[rowi * HID + k]), sM1[k * HG + chg]);
        } else {
            int r2 = rowi - 144;
#pragma unroll
            for (int k = 0; k < HID; k++)
                fma4(acc, __ldg(&W2[r2 * HID + k]), sM1[(HID + k) * HG + chg]);
        }
        ((float4*)g_C)[rowi * HG + chg] = acc;
    }
    if (blockIdx.x == 0 && tid < HG) {
        float4 acc = __ldg(&((const float4*)bm)[tid]);
#pragma unroll 8
        for (int k = 0; k < HID; k++) {
            fma4(acc, __ldg(&b1[k]), sM1[k * HG + tid]);
            fma4(acc, __ldg(&b2[k]), sM1[(HID + k) * HG + tid]);
        }
        ((float4*)g_bz)[tid] = acc;
    }
}

// final per-edge stage: z = U[r] + V[c] + attr@C3 + bz; out = tanh(z).w2 + b2m
// 2-tile partial buffering: 2 syncs per 32 edges; c3 (64 regs) per-thread.
__global__ void __launch_bounds__(288, 2) k_edge(const int* __restrict__ row,
                                                 const int* __restrict__ col,
                                                 const float* __restrict__ attr,
                                                 const float* __restrict__ w2,
                                                 const float* __restrict__ b2m,
                                                 float* __restrict__ out) {
    __shared__ float shp[2][288];
    int tid = threadIdx.x;
    int el = tid / HG;          // 0..15
    int chg = tid - el * HG;    // 0..17
    const float4* C3_4 = (const float4*)(g_C + 144 * HID);
    float4 c3[16];
#pragma unroll
    for (int k = 0; k < 16; k++) c3[k] = __ldg(&C3_4[k * HG + chg]);
    float4 bz = __ldg(&((const float4*)g_bz)[chg]);
    float4 wv = __ldg(&((const float4*)w2)[chg]);
    float bout = __ldg(b2m);
    const float4* U4 = (const float4*)g_m;
    const float4* V4 = (const float4*)g_agg;
    const float4* a4 = (const float4*)attr;
    const int nrounds = NE / 32;   // 25000
    for (int rd = blockIdx.x; rd < nrounds; rd += gridDim.x) {
#pragma unroll
        for (int s = 0; s < 2; s++) {
            int e = rd * 32 + s * 16 + el;
            int r = __ldg(&row[e]);
            int c = __ldg(&col[e]);
            float4 u = __ldg(&U4[r * HG + chg]);
            float4 v = __ldg(&V4[c * HG + chg]);
            float4 z;
            z.x = u.x + v.x + bz.x;
            z.y = u.y + v.y + bz.y;
            z.z = u.z + v.z + bz.z;
            z.w = u.w + v.w + bz.w;
            float4 a0 = __ldg(&a4[e * 4 + 0]);
            float4 a1 = __ldg(&a4[e * 4 + 1]);
            float4 a2 = __ldg(&a4[e * 4 + 2]);
            float4 a3 = __ldg(&a4[e * 4 + 3]);
            fma4(z, a0.x, c3[0]);  fma4(z, a0.y, c3[1]);  fma4(z, a0.z, c3[2]);  fma4(z, a0.w, c3[3]);
            fma4(z, a1.x, c3[4]);  fma4(z, a1.y, c3[5]);  fma4(z, a1.z, c3[6]);  fma4(z, a1.w, c3[7]);
            fma4(z, a2.x, c3[8]);  fma4(z, a2.y, c3[9]);  fma4(z, a2.z, c3[10]); fma4(z, a2.w, c3[11]);
            fma4(z, a3.x, c3[12]); fma4(z, a3.y, c3[13]); fma4(z, a3.z, c3[14]); fma4(z, a3.w, c3[15]);
            shp[s][tid] = tanh_fast(z.x) * wv.x + tanh_fast(z.y) * wv.y +
                          tanh_fast(z.z) * wv.z + tanh_fast(z.w) * wv.w;
        }
        __syncthreads();
        if (tid < 32) {
            int sSel = tid >> 4, e_l = tid & 15;
            float ss = 0.f;
#pragma unroll
            for (int jj = 0; jj < HG; jj++) ss += shp[sSel][e_l * HG + jj];
            out[rd * 32 + tid] = ss + bout;
        }
        __syncthreads();
    }
}

// ---------------- launch ----------------
extern "C" void kernel_launch(void* const* d_in, const int* in_sizes, int n_in,
                              void* d_out, int out_size) {
    const float* x     = (const float*)d_in[0];
    const int*   ei    = (const int*)d_in[1];
    const float* attr  = (const float*)d_in[2];
    const float* nlw   = (const float*)d_in[3];
    const float* nlb   = (const float*)d_in[4];
    const float* convw = (const float*)d_in[5];
    const float* convv = (const float*)d_in[6];
    const float* convb = (const float*)d_in[7];
    const float* gamma = (const float*)d_in[8];
    const float* beta  = (const float*)d_in[9];
    const float* W1    = (const float*)d_in[10];
    const float* b1    = (const float*)d_in[11];
    const float* W2    = (const float*)d_in[12];
    const float* b2e   = (const float*)d_in[13];
    const float* M1    = (const float*)d_in[14];
    const float* bm    = (const float*)d_in[15];
    const float* w2    = (const float*)d_in[16];
    const float* b2m   = (const float*)d_in[17];
    const int* row = ei;
    const int* col = ei + NE;
    float* out = (float*)d_out;

    float* pC = nullptr;
    float* pScale = nullptr;
    float* pShift = nullptr;
    cudaGetSymbolAddress((void**)&pC, g_C);
    cudaGetSymbolAddress((void**)&pScale, g_scale);
    cudaGetSymbolAddress((void**)&pShift, g_shift);

    const int GB = (NN + 63) / 64;  // 782 blocks, 64 nodes each

    k_zero_deg<<<(NN + 255) / 256, 256>>>();
    k_deg<<<(NE + 255) / 256, 256>>>(col);
    k_scan<<<1, 1024>>>();
    k_sort<<<(NE + 255) / 256, 256>>>(row, col);
    k_node_lin<<<GB, 288>>>(x, nlw, nlb);
    for (int t = 0; t < NLAY; t++) {
        k_dualgemm<<<GB, 288>>>(convw + t * HID * HID, convv + t * HID * HID,
                                convb + t * HID,
                                t == 0 ? nullptr : pScale,
                                t == 0 ? nullptr : pShift);
        k_aggregate<<<3125, dim3(HG, 16)>>>();
        k_bn_final<<<1, HID>>>(gamma + t * HID, beta + t * HID);
    }
    k_fold<<<10, 288>>>(W1, W2, M1, b1, b2e, bm);
    k_dualgemm<<<GB, 288>>>(pC, pC + HID * HID, nullptr, pScale, pShift);
    k_edge<<<1850, 288>>>(row, col, attr, w2, b2m, out);
}

// round 4
// speedup vs baseline: 1.4305x; 1.0148x over previous
#include <cuda_runtime.h>
#include <cuda_fp16.h>

#define NN   50000
#define NE   800000
#define FIN  128
#define HID  72
#define HG   18      // HID/4
#define NLAY 3

// ---------------- scratch (static __device__, no allocations) ----------------
__device__ int   g_degi[NN];
__device__ float g_dinv[NN];
__device__ int   g_off[NN + 1];
__device__ int   g_cur[NN];
__device__ int2  g_edge[NE];          // {src row, __float_as_int(norm)} CSR-by-col
__device__ float g_h[NN * HID];
__device__ float g_m[NN * HID];
__device__ float g_agg[NN * HID];
__device__ float g_statsL[NLAY][2 * HID];  // per-layer BN stats (zeroed each call)
__device__ float g_C[160 * HID];      // folded weights
__device__ float g_bz[HID];
__device__ uint2 g_mh[NN * HG];       // U as packed half (4 halves per uint2)
__device__ uint2 g_aggh[NN * HG];     // V as packed half

// ---------------- helpers ----------------
__device__ __forceinline__ void fma4(float4& a, float s, const float4& b) {
    a.x = __fmaf_rn(s, b.x, a.x);
    a.y = __fmaf_rn(s, b.y, a.y);
    a.z = __fmaf_rn(s, b.z, a.z);
    a.w = __fmaf_rn(s, b.w, a.w);
}
__device__ __forceinline__ float tanh_fast(float x) {
    float e = __expf(2.0f * x);
    return 1.0f - __fdividef(2.0f, e + 1.0f);
}

// ---------------- graph preprocessing ----------------
__global__ void k_zero() {
    int i = blockIdx.x * blockDim.x + threadIdx.x;
    if (i < NN) g_degi[i] = 0;
    if (i < NLAY * 2 * HID) ((float*)g_statsL)[i] = 0.f;
}
__global__ void k_deg(const int* __restrict__ col) {
    int e = blockIdx.x * blockDim.x + threadIdx.x;
    if (e < NE) atomicAdd(&g_degi[col[e]], 1);
}
__global__ void k_scan() {
    __shared__ int sp[1024];
    int tid = threadIdx.x;
    const int CH = (NN + 1023) / 1024;  // 49
    int start = tid * CH;
    int end = min(start + CH, NN);
    int loc = 0;
    for (int i = start; i < end; i++) loc += g_degi[i];
    sp[tid] = loc;
    __syncthreads();
    for (int off = 1; off < 1024; off <<= 1) {
        int v = (tid >= off) ? sp[tid - off] : 0;
        __syncthreads();
        sp[tid] += v;
        __syncthreads();
    }
    int run = sp[tid] - loc;
    for (int i = start; i < end; i++) {
        int d = g_degi[i];
        g_off[i] = run;
        g_cur[i] = run;
        run += d;
        g_dinv[i] = (d > 0) ? rsqrtf((float)d) : 0.0f;
    }
    if (tid == 1023) g_off[NN] = NE;
}
__global__ void k_sort(const int* __restrict__ row, const int* __restrict__ col) {
    int e = blockIdx.x * blockDim.x + threadIdx.x;
    if (e < NE) {
        int r = row[e], c = col[e];
        float nrm = g_dinv[r] * g_dinv[c];
        int p = atomicAdd(&g_cur[c], 1);
        g_edge[p] = make_int2(r, __float_as_int(nrm));
    }
}

// ---------------- node GEMMs ----------------
// h = relu(x @ W + b). 64 nodes/block, 4 nodes/thread, K chunked by 32.
__global__ void __launch_bounds__(288) k_node_lin(const float* __restrict__ x,
                                                  const float* __restrict__ W,
                                                  const float* __restrict__ b) {
    __shared__ float4 sW[32 * HG];
    __shared__ float4 sx[64 * 9];
    int tid = threadIdx.x;
    int tx = tid % HG, ty = tid / HG;
    int n0 = blockIdx.x * 64;
    const float4* W4 = (const float4*)W;
    const float4* x4 = (const float4*)x;
    float4 acc[4];
    float4 bb = __ldg(&((const float4*)b)[tx]);
#pragma unroll
    for (int i = 0; i < 4; i++) acc[i] = bb;

    for (int c = 0; c < 4; c++) {
        __syncthreads();
        for (int i = tid; i < 32 * HG; i += 288) {
            int kk = i / HG, j = i % HG;
            sW[i] = W4[(c * 32 + kk) * HG + j];
        }
        for (int i = tid; i < 64 * 8; i += 288) {
            int r = i >> 3, kq = i & 7;
            int n = n0 + r;
            float4 v = make_float4(0.f, 0.f, 0.f, 0.f);
            if (n < NN) v = x4[n * 32 + c * 8 + kq];
            sx[r * 9 + kq] = v;
        }
        __syncthreads();
        const float* sxf = (const float*)sx;
#pragma unroll 8
        for (int k = 0; k < 32; k++) {
            float4 w = sW[k * HG + tx];
#pragma unroll
            for (int i = 0; i < 4; i++)
                fma4(acc[i], sxf[(ty * 4 + i) * 36 + k], w);
        }
    }
#pragma unroll
    for (int i = 0; i < 4; i++) {
        int n = n0 + ty * 4 + i;
        if (n < NN) {
            float4 a = acc[i];
            a.x = fmaxf(a.x, 0.f); a.y = fmaxf(a.y, 0.f);
            a.z = fmaxf(a.z, 0.f); a.w = fmaxf(a.w, 0.f);
            ((float4*)g_h)[n * HG + tx] = a;
        }
    }
}

// [m | agg] = bn(h) @ [Wa | Wb] (+bias on Wb half). BN scale/shift computed
// in-kernel from stats (if gamma != null). Optional fp16-packed output.
__global__ void __launch_bounds__(288) k_dualgemm(const float* __restrict__ Wa,
                                                  const float* __restrict__ Wb,
                                                  const float* __restrict__ bias,
                                                  const float* __restrict__ gamma,
                                                  const float* __restrict__ beta,
                                                  const float* __restrict__ stats,
                                                  int half_out) {
    __shared__ float4 sW[36 * 36];
    __shared__ float4 sx[64 * 10];
    __shared__ float s_scale[HID], s_shift[HID];
    int tid = threadIdx.x;
    int tx = tid % 36, ty = tid / 36;
    int n0 = blockIdx.x * 64;
    const float4* Wa4 = (const float4*)Wa;
    const float4* Wb4 = (const float4*)Wb;
    const float4* h4 = (const float4*)g_h;
    const int use_bn = (gamma != nullptr);

    if (use_bn && tid < HID) {
        float S = __ldg(&stats[tid]), Q = __ldg(&stats[HID + tid]);
        float mu = S * (1.0f / NN);
        float var = Q * (1.0f / NN) - mu * mu;
        float sc = __ldg(&gamma[tid]) * rsqrtf(var + 1e-5f);
        s_scale[tid] = sc;
        s_shift[tid] = __ldg(&beta[tid]) - mu * sc;
    }

    float4 acc[8];
    float4 binit = make_float4(0.f, 0.f, 0.f, 0.f);
    if (bias != nullptr && tx >= HG) binit = __ldg(&((const float4*)bias)[tx - HG]);
#pragma unroll
    for (int i = 0; i < 8; i++) acc[i] = binit;

    for (int c = 0; c < 2; c++) {
        __syncthreads();   // first iteration also publishes s_scale/s_shift
        for (int i = tid; i < 36 * 36; i += 288) {
            int kk = i / 36, j = i % 36;
            sW[i] = (j < HG) ? Wa4[(c * 36 + kk) * HG + j]
                             : Wb4[(c * 36 + kk) * HG + j - HG];
        }
        for (int i = tid; i < 64 * 9; i += 288) {
            int r = i / 9, kq = i % 9;
            int n = n0 + r;
            float4 v = make_float4(0.f, 0.f, 0.f, 0.f);
            if (n < NN) {
                v = h4[n * HG + c * 9 + kq];
                if (use_bn) {
                    int k0 = (c * 9 + kq) * 4;
                    v.x = __fmaf_rn(v.x, s_scale[k0 + 0], s_shift[k0 + 0]);
                    v.y = __fmaf_rn(v.y, s_scale[k0 + 1], s_shift[k0 + 1]);
                    v.z = __fmaf_rn(v.z, s_scale[k0 + 2], s_shift[k0 + 2]);
                    v.w = __fmaf_rn(v.w, s_scale[k0 + 3], s_shift[k0 + 3]);
                }
            }
            sx[r * 10 + kq] = v;
        }
        __syncthreads();
        const float* sxf = (const float*)sx;
#pragma unroll 4
        for (int k = 0; k < 36; k++) {
            float4 w = sW[k * 36 + tx];
#pragma unroll
            for (int i = 0; i < 8; i++)
                fma4(acc[i], sxf[(ty * 8 + i) * 40 + k], w);
        }
    }
    if (!half_out) {
        float4* m4 = (float4*)g_m;
        float4* agg4 = (float4*)g_agg;
#pragma unroll
        for (int i = 0; i < 8; i++) {
            int n = n0 + ty * 8 + i;
            if (n < NN) {
                if (tx < HG) m4[n * HG + tx] = acc[i];
                else         agg4[n * HG + tx - HG] = acc[i];
            }
        }
    } else {
#pragma unroll
        for (int i = 0; i < 8; i++) {
            int n = n0 + ty * 8 + i;
            if (n < NN) {
                __half2 lo = __floats2half2_rn(acc[i].x, acc[i].y);
                __half2 hi = __floats2half2_rn(acc[i].z, acc[i].w);
                uint2 p = make_uint2(*reinterpret_cast<unsigned*>(&lo),
                                     *reinterpret_cast<unsigned*>(&hi));
                if (tx < HG) g_mh[n * HG + tx] = p;
                else         g_aggh[n * HG + tx - HG] = p;
            }
        }
    }
}

// gather aggregation + relu + BN-stats fused. 16 nodes/block.
__global__ void __launch_bounds__(288) k_aggregate(float* __restrict__ stats) {
    int tx = threadIdx.x, ty = threadIdx.y;
    int n = blockIdx.x * 16 + ty;     // NN = 3125*16 exact
    int s = g_off[n], e = g_off[n + 1];
    const float4* m4 = (const float4*)g_m;
    float4 acc = ((const float4*)g_agg)[n * HG + tx];
    int j = s;
    for (; j + 3 < e; j += 4) {
        int2 e0 = __ldg(&g_edge[j]);
        int2 e1 = __ldg(&g_edge[j + 1]);
        int2 e2 = __ldg(&g_edge[j + 2]);
        int2 e3 = __ldg(&g_edge[j + 3]);
        float4 v0 = __ldg(&m4[e0.x * HG + tx]);
        float4 v1 = __ldg(&m4[e1.x * HG + tx]);
        float4 v2 = __ldg(&m4[e2.x * HG + tx]);
        float4 v3 = __ldg(&m4[e3.x * HG + tx]);
        fma4(acc, __int_as_float(e0.y), v0);
        fma4(acc, __int_as_float(e1.y), v1);
        fma4(acc, __int_as_float(e2.y), v2);
        fma4(acc, __int_as_float(e3.y), v3);
    }
    for (; j < e; j++) {
        int2 e0 = __ldg(&g_edge[j]);
        fma4(acc, __int_as_float(e0.y), __ldg(&m4[e0.x * HG + tx]));
    }
    acc.x = fmaxf(acc.x, 0.f); acc.y = fmaxf(acc.y, 0.f);
    acc.z = fmaxf(acc.z, 0.f); acc.w = fmaxf(acc.w, 0.f);
    ((float4*)g_h)[n * HG + tx] = acc;

    __shared__ float4 red[2][16][19];
    float4 sq;
    sq.x = acc.x * acc.x; sq.y = acc.y * acc.y;
    sq.z = acc.z * acc.z; sq.w = acc.w * acc.w;
    red[0][ty][tx] = acc;
    red[1][ty][tx] = sq;
    __syncthreads();
    if (ty == 0) {
        float4 S = make_float4(0.f, 0.f, 0.f, 0.f);
        float4 Q = make_float4(0.f, 0.f, 0.f, 0.f);
#pragma unroll
        for (int r = 0; r < 16; r++) {
            float4 a = red[0][r][tx], q = red[1][r][tx];
            S.x += a.x; S.y += a.y; S.z += a.z; S.w += a.w;
            Q.x += q.x; Q.y += q.y; Q.z += q.z; Q.w += q.w;
        }
        atomicAdd(&stats[tx * 4 + 0], S.x);
        atomicAdd(&stats[tx * 4 + 1], S.y);
        atomicAdd(&stats[tx * 4 + 2], S.z);
        atomicAdd(&stats[tx * 4 + 3], S.w);
        atomicAdd(&stats[HID + tx * 4 + 0], Q.x);
        atomicAdd(&stats[HID + tx * 4 + 1], Q.y);
        atomicAdd(&stats[HID + tx * 4 + 2], Q.z);
        atomicAdd(&stats[HID + tx * 4 + 3], Q.w);
    }
}

// fold edge-MLP front-end: C[160][72], bz[72]
__global__ void __launch_bounds__(288) k_fold(const float* __restrict__ W1,
                                              const float* __restrict__ W2,
                                              const float* __restrict__ M1,
                                              const float* __restrict__ b1,
                                              const float* __restrict__ b2,
                                              const float* __restrict__ bm) {
    __shared__ float4 sM1[144 * HG];
    int tid = threadIdx.x;
    const float4* M1_4 = (const float4*)M1;
    for (int i = tid; i < 144 * HG; i += 288) sM1[i] = M1_4[i];
    __syncthreads();
    int rowi = blockIdx.x * 16 + tid / HG;
    int chg = tid % HG;
    if (rowi < 160) {
        float4 acc = make_float4(0.f, 0.f, 0.f, 0.f);
        if (rowi < 144) {
#pragma unroll 8
            for (int k = 0; k < HID; k++)
                fma4(acc, __ldg(&W1[rowi * HID + k]), sM1[k * HG + chg]);
        } else {
            int r2 = rowi - 144;
#pragma unroll
            for (int k = 0; k < HID; k++)
                fma4(acc, __ldg(&W2[r2 * HID + k]), sM1[(HID + k) * HG + chg]);
        }
        ((float4*)g_C)[rowi * HG + chg] = acc;
    }
    if (blockIdx.x == 0 && tid < HG) {
        float4 acc = __ldg(&((const float4*)bm)[tid]);
#pragma unroll 8
        for (int k = 0; k < HID; k++) {
            fma4(acc, __ldg(&b1[k]), sM1[k * HG + tid]);
            fma4(acc, __ldg(&b2[k]), sM1[(HID + k) * HG + tid]);
        }
        ((float4*)g_bz)[tid] = acc;
    }
}

// final per-edge stage: z = U[r] + V[c] + attr@C3 + bz; out = tanh(z).w2 + b2m
// 4-tile buffering: 2 syncs per 64 edges; U/V are fp16-packed (8B per thread).
__global__ void __launch_bounds__(288, 2) k_edge(const int* __restrict__ row,
                                                 const int* __restrict__ col,
                                                 const float* __restrict__ attr,
                                                 const float* __restrict__ w2,
                                                 const float* __restrict__ b2m,
                                                 float* __restrict__ out) {
    __shared__ float shp[4][288];
    int tid = threadIdx.x;
    int el = tid / HG;          // 0..15
    int chg = tid - el * HG;    // 0..17
    const float4* C3_4 = (const float4*)(g_C + 144 * HID);
    float4 c3[16];
#pragma unroll
    for (int k = 0; k < 16; k++) c3[k] = __ldg(&C3_4[k * HG + chg]);
    float4 bz = __ldg(&((const float4*)g_bz)[chg]);
    float4 wv = __ldg(&((const float4*)w2)[chg]);
    float bout = __ldg(b2m);
    const float4* a4 = (const float4*)attr;
    const int nrounds = NE / 64;   // 12500
    for (int rd = blockIdx.x; rd < nrounds; rd += gridDim.x) {
        int ebase = rd * 64 + el;
#pragma unroll
        for (int s = 0; s < 4; s++) {
            int e = ebase + s * 16;
            int r = __ldg(&row[e]);
            int c = __ldg(&col[e]);
            uint2 up = __ldg(&g_mh[r * HG + chg]);
            uint2 vp = __ldg(&g_aggh[c * HG + chg]);
            float2 ulo = __half22float2(*reinterpret_cast<__half2*>(&up.x));
            float2 uhi = __half22float2(*reinterpret_cast<__half2*>(&up.y));
            float2 vlo = __half22float2(*reinterpret_cast<__half2*>(&vp.x));
            float2 vhi = __half22float2(*reinterpret_cast<__half2*>(&vp.y));
            float4 z;
            z.x = ulo.x + vlo.x + bz.x;
            z.y = ulo.y + vlo.y + bz.y;
            z.z = uhi.x + vhi.x + bz.z;
            z.w = uhi.y + vhi.y + bz.w;
            float4 a0 = __ldg(&a4[e * 4 + 0]);
            float4 a1 = __ldg(&a4[e * 4 + 1]);
            float4 a2 = __ldg(&a4[e * 4 + 2]);
            float4 a3 = __ldg(&a4[e * 4 + 3]);
            fma4(z, a0.x, c3[0]);  fma4(z, a0.y, c3[1]);  fma4(z, a0.z, c3[2]);  fma4(z, a0.w, c3[3]);
            fma4(z, a1.x, c3[4]);  fma4(z, a1.y, c3[5]);  fma4(z, a1.z, c3[6]);  fma4(z, a1.w, c3[7]);
            fma4(z, a2.x, c3[8]);  fma4(z, a2.y, c3[9]);  fma4(z, a2.z, c3[10]); fma4(z, a2.w, c3[11]);
            fma4(z, a3.x, c3[12]); fma4(z, a3.y, c3[13]); fma4(z, a3.z, c3[14]); fma4(z, a3.w, c3[15]);
            shp[s][tid] = tanh_fast(z.x) * wv.x + tanh_fast(z.y) * wv.y +
                          tanh_fast(z.z) * wv.z + tanh_fast(z.w) * wv.w;
        }
        __syncthreads();
        if (tid < 64) {
            int sSel = tid >> 4, e_l = tid & 15;
            float ss = 0.f;
#pragma unroll
            for (int jj = 0; jj < HG; jj++) ss += shp[sSel][e_l * HG + jj];
            out[rd * 64 + tid] = ss + bout;
        }
        __syncthreads();
    }
}

// ---------------- launch ----------------
extern "C" void kernel_launch(void* const* d_in, const int* in_sizes, int n_in,
                              void* d_out, int out_size) {
    const float* x     = (const float*)d_in[0];
    const int*   ei    = (const int*)d_in[1];
    const float* attr  = (const float*)d_in[2];
    const float* nlw   = (const float*)d_in[3];
    const float* nlb   = (const float*)d_in[4];
    const float* convw = (const float*)d_in[5];
    const float* convv = (const float*)d_in[6];
    const float* convb = (const float*)d_in[7];
    const float* gamma = (const float*)d_in[8];
    const float* beta  = (const float*)d_in[9];
    const float* W1    = (const float*)d_in[10];
    const float* b1    = (const float*)d_in[11];
    const float* W2    = (const float*)d_in[12];
    const float* b2e   = (const float*)d_in[13];
    const float* M1    = (const float*)d_in[14];
    const float* bm    = (const float*)d_in[15];
    const float* w2    = (const float*)d_in[16];
    const float* b2m   = (const float*)d_in[17];
    const int* row = ei;
    const int* col = ei + NE;
    float* out = (float*)d_out;

    float* pC = nullptr;
    float* pStats = nullptr;
    cudaGetSymbolAddress((void**)&pC, g_C);
    cudaGetSymbolAddress((void**)&pStats, g_statsL);

    const int GB = (NN + 63) / 64;  // 782 blocks, 64 nodes each

    // Order: node_lin/dualgemm0 moved ahead of CSR build so the ncu window
    // (0-based launch #3) captures k_dualgemm.
    k_zero<<<(NN + 255) / 256, 256>>>();                                   // 0
    k_deg<<<(NE + 255) / 256, 256>>>(col);                                 // 1
    k_node_lin<<<GB, 288>>>(x, nlw, nlb);                                  // 2
    k_dualgemm<<<GB, 288>>>(convw, convv, convb,                           // 3 (profiled)
                            nullptr, nullptr, nullptr, 0);
    k_scan<<<1, 1024>>>();                                                 // 4
    k_sort<<<(NE + 255) / 256, 256>>>(row, col);                           // 5
    k_aggregate<<<3125, dim3(HG, 16)>>>(pStats);                           // 6
    for (int t = 1; t < NLAY; t++) {
        k_dualgemm<<<GB, 288>>>(convw + t * HID * HID, convv + t * HID * HID,
                                convb + t * HID,
                                gamma + (t - 1) * HID, beta + (t - 1) * HID,
                                pStats + (t - 1) * 2 * HID, 0);
        k_aggregate<<<3125, dim3(HG, 16)>>>(pStats + t * 2 * HID);
    }
    k_fold<<<10, 288>>>(W1, W2, M1, b1, b2e, bm);                          // 11
    k_dualgemm<<<GB, 288>>>(pC, pC + HID * HID, nullptr,                   // 12
                            gamma + (NLAY - 1) * HID, beta + (NLAY - 1) * HID,
                            pStats + (NLAY - 1) * 2 * HID, 1);
    k_edge<<<1850, 288>>>(row, col, attr, w2, b2m, out);                   // 13
}

// round 5
// speedup vs baseline: 1.4515x; 1.0147x over previous
#include <cuda_runtime.h>
#include <cuda_fp16.h>

#define NN   50000
#define NE   800000
#define FIN  128
#define HID  72
#define HG   18      // HID/4
#define NLAY 3

// ---------------- scratch (static __device__, no allocations) ----------------
__device__ int   g_degi[NN];
__device__ float g_dinv[NN];
__device__ int   g_off[NN + 1];
__device__ int   g_cur[NN];
__device__ int2  g_edge[NE];          // {src row, __float_as_int(norm)} CSR-by-col
__device__ float g_h[NN * HID];
__device__ float g_m[NN * HID];
__device__ float g_agg[NN * HID];
__device__ float g_statsL[NLAY][2 * HID];
__device__ float g_C[160 * HID];      // folded weights
__device__ float g_bz[HID];
__device__ uint2 g_mh[NN * HG];       // U as packed half
__device__ uint2 g_aggh[NN * HG];     // V as packed half

// ---------------- helpers ----------------
__device__ __forceinline__ void fma4(float4& a, float s, const float4& b) {
    a.x = __fmaf_rn(s, b.x, a.x);
    a.y = __fmaf_rn(s, b.y, a.y);
    a.z = __fmaf_rn(s, b.z, a.z);
    a.w = __fmaf_rn(s, b.w, a.w);
}
__device__ __forceinline__ float tanh_fast(float x) {
    float e = __expf(2.0f * x);
    return 1.0f - __fdividef(2.0f, e + 1.0f);
}

// ---------------- graph preprocessing ----------------
__global__ void k_zero() {
    int i = blockIdx.x * blockDim.x + threadIdx.x;
    if (i < NN) g_degi[i] = 0;
    if (i < NLAY * 2 * HID) ((float*)g_statsL)[i] = 0.f;
}
__global__ void k_deg(const int* __restrict__ col) {
    int e = blockIdx.x * blockDim.x + threadIdx.x;
    if (e < NE) atomicAdd(&g_degi[col[e]], 1);
}
__global__ void k_scan() {
    __shared__ int sp[1024];
    int tid = threadIdx.x;
    const int CH = (NN + 1023) / 1024;  // 49
    int start = tid * CH;
    int end = min(start + CH, NN);
    int loc = 0;
    for (int i = start; i < end; i++) loc += g_degi[i];
    sp[tid] = loc;
    __syncthreads();
    for (int off = 1; off < 1024; off <<= 1) {
        int v = (tid >= off) ? sp[tid - off] : 0;
        __syncthreads();
        sp[tid] += v;
        __syncthreads();
    }
    int run = sp[tid] - loc;
    for (int i = start; i < end; i++) {
        int d = g_degi[i];
        g_off[i] = run;
        g_cur[i] = run;
        run += d;
        g_dinv[i] = (d > 0) ? rsqrtf((float)d) : 0.0f;
    }
    if (tid == 1023) g_off[NN] = NE;
}
__global__ void k_sort(const int* __restrict__ row, const int* __restrict__ col) {
    int e = blockIdx.x * blockDim.x + threadIdx.x;
    if (e < NE) {
        int r = row[e], c = col[e];
        float nrm = g_dinv[r] * g_dinv[c];
        int p = atomicAdd(&g_cur[c], 1);
        g_edge[p] = make_int2(r, __float_as_int(nrm));
    }
}

// ---------------- node GEMMs (2-D register tiles, x transposed in smem) ----------------
// h = relu(x @ W + b). 128 nodes/block; thread = 4 nodes x 2 f4-cols.
// Block 288 = 9 tx (cols tx, tx+9) x 32 ty (nodes ty*4..+3). K chunked 4x32.
__global__ void __launch_bounds__(288) k_node_lin(const float* __restrict__ x,
                                                  const float* __restrict__ W,
                                                  const float* __restrict__ b) {
    __shared__ float4 sW[32 * HG];       // 9216B
    __shared__ float  sxT[32 * 130];     // 16640B, [k][node] transposed, pad 130
    int tid = threadIdx.x;
    int tx = tid % 9, ty = tid / 9;      // ty 0..31
    int n0 = blockIdx.x * 128;
    const float4* W4 = (const float4*)W;
    const float4* x4 = (const float4*)x;
    float4 acc0[4], acc1[4];
    float4 b0 = __ldg(&((const float4*)b)[tx]);
    float4 b1 = __ldg(&((const float4*)b)[tx + 9]);
#pragma unroll
    for (int i = 0; i < 4; i++) { acc0[i] = b0; acc1[i] = b1; }

    for (int c = 0; c < 4; c++) {
        __syncthreads();
        for (int i = tid; i < 32 * HG; i += 288) {
            int kk = i / HG, j = i % HG;
            sW[i] = W4[(c * 32 + kk) * HG + j];
        }
        for (int i = tid; i < 128 * 8; i += 288) {
            int n = i >> 3, kq = i & 7;
            int gn = n0 + n;
            float4 v = make_float4(0.f, 0.f, 0.f, 0.f);
            if (gn < NN) v = x4[gn * 32 + c * 8 + kq];
            sxT[(4 * kq + 0) * 130 + n] = v.x;
            sxT[(4 * kq + 1) * 130 + n] = v.y;
            sxT[(4 * kq + 2) * 130 + n] = v.z;
            sxT[(4 * kq + 3) * 130 + n] = v.w;
        }
        __syncthreads();
#pragma unroll 4
        for (int k = 0; k < 32; k++) {
            float4 w0 = sW[k * HG + tx];
            float4 w1 = sW[k * HG + tx + 9];
            float xv[4];
#pragma unroll
            for (int i = 0; i < 4; i++) xv[i] = sxT[k * 130 + ty * 4 + i];
#pragma unroll
            for (int i = 0; i < 4; i++) {
                fma4(acc0[i], xv[i], w0);
                fma4(acc1[i], xv[i], w1);
            }
        }
    }
    float4* h4 = (float4*)g_h;
#pragma unroll
    for (int i = 0; i < 4; i++) {
        int n = n0 + ty * 4 + i;
        if (n < NN) {
            float4 a = acc0[i];
            a.x = fmaxf(a.x, 0.f); a.y = fmaxf(a.y, 0.f);
            a.z = fmaxf(a.z, 0.f); a.w = fmaxf(a.w, 0.f);
            h4[n * HG + tx] = a;
            a = acc1[i];
            a.x = fmaxf(a.x, 0.f); a.y = fmaxf(a.y, 0.f);
            a.z = fmaxf(a.z, 0.f); a.w = fmaxf(a.w, 0.f);
            h4[n * HG + tx + 9] = a;
        }
    }
}

// [m | agg] = bn(h) @ [Wa | Wb] (+bias on agg half). 128 nodes/block;
// thread = 8 nodes x 2 f4-cols (acc0 -> m col tx, acc1 -> agg col tx).
// Block 288 = 18 tx x 16 ty. K chunked 2x36.
__global__ void __launch_bounds__(288, 2) k_dualgemm(const float* __restrict__ Wa,
                                                     const float* __restrict__ Wb,
                                                     const float* __restrict__ bias,
                                                     const float* __restrict__ gamma,
                                                     const float* __restrict__ beta,
                                                     const float* __restrict__ stats,
                                                     int half_out) {
    __shared__ float4 sW[36 * 36];       // 20736B: [k][j<18: Wa, j>=18: Wb]
    __shared__ float  sxT[36 * 130];     // 18720B: [k][node], pad 130
    __shared__ float  s_scale[HID], s_shift[HID];
    int tid = threadIdx.x;
    int tx = tid % HG, ty = tid / HG;    // ty 0..15
    int n0 = blockIdx.x * 128;
    const float4* Wa4 = (const float4*)Wa;
    const float4* Wb4 = (const float4*)Wb;
    const float4* h4 = (const float4*)g_h;
    const int use_bn = (gamma != nullptr);

    if (use_bn && tid < HID) {
        float S = __ldg(&stats[tid]), Q = __ldg(&stats[HID + tid]);
        float mu = S * (1.0f / NN);
        float var = Q * (1.0f / NN) - mu * mu;
        float sc = __ldg(&gamma[tid]) * rsqrtf(var + 1e-5f);
        s_scale[tid] = sc;
        s_shift[tid] = __ldg(&beta[tid]) - mu * sc;
    }

    float4 acc0[8], acc1[8];
    float4 b1 = (bias != nullptr) ? __ldg(&((const float4*)bias)[tx])
                                  : make_float4(0.f, 0.f, 0.f, 0.f);
#pragma unroll
    for (int i = 0; i < 8; i++) {
        acc0[i] = make_float4(0.f, 0.f, 0.f, 0.f);
        acc1[i] = b1;
    }

    for (int c = 0; c < 2; c++) {
        __syncthreads();   // first iteration also publishes s_scale/s_shift
        for (int i = tid; i < 36 * 36; i += 288) {
            int kk = i / 36, j = i % 36;
            sW[i] = (j < HG) ? Wa4[(c * 36 + kk) * HG + j]
                             : Wb4[(c * 36 + kk) * HG + j - HG];
        }
        for (int i = tid; i < 128 * 9; i += 288) {
            int n = i / 9, kq = i % 9;
            int gn = n0 + n;
            float4 v = make_float4(0.f, 0.f, 0.f, 0.f);
            if (gn < NN) {
                v = h4[gn * HG + c * 9 + kq];
                if (use_bn) {
                    int k0 = (c * 9 + kq) * 4;
                    v.x = __fmaf_rn(v.x, s_scale[k0 + 0], s_shift[k0 + 0]);
                    v.y = __fmaf_rn(v.y, s_scale[k0 + 1], s_shift[k0 + 1]);
                    v.z = __fmaf_rn(v.z, s_scale[k0 + 2], s_shift[k0 + 2]);
                    v.w = __fmaf_rn(v.w, s_scale[k0 + 3], s_shift[k0 + 3]);
                }
            }
            sxT[(4 * kq + 0) * 130 + n] = v.x;
            sxT[(4 * kq + 1) * 130 + n] = v.y;
            sxT[(4 * kq + 2) * 130 + n] = v.z;
            sxT[(4 * kq + 3) * 130 + n] = v.w;
        }
        __syncthreads();
#pragma unroll 4
        for (int k = 0; k < 36; k++) {
            float4 w0 = sW[k * 36 + tx];
            float4 w1 = sW[k * 36 + 18 + tx];
            float xv[8];
#pragma unroll
            for (int i = 0; i < 8; i++) xv[i] = sxT[k * 130 + ty * 8 + i];
#pragma unroll
            for (int i = 0; i < 8; i++) {
                fma4(acc0[i], xv[i], w0);
                fma4(acc1[i], xv[i], w1);
            }
        }
    }
    if (!half_out) {
        float4* m4 = (float4*)g_m;
        float4* agg4 = (float4*)g_agg;
#pragma unroll
        for (int i = 0; i < 8; i++) {
            int n = n0 + ty * 8 + i;
            if (n < NN) {
                m4[n * HG + tx] = acc0[i];
                agg4[n * HG + tx] = acc1[i];
            }
        }
    } else {
#pragma unroll
        for (int i = 0; i < 8; i++) {
            int n = n0 + ty * 8 + i;
            if (n < NN) {
                __half2 lo = __floats2half2_rn(acc0[i].x, acc0[i].y);
                __half2 hi = __floats2half2_rn(acc0[i].z, acc0[i].w);
                g_mh[n * HG + tx] = make_uint2(*reinterpret_cast<unsigned*>(&lo),
                                               *reinterpret_cast<unsigned*>(&hi));
                lo = __floats2half2_rn(acc1[i].x, acc1[i].y);
                hi = __floats2half2_rn(acc1[i].z, acc1[i].w);
                g_aggh[n * HG + tx] = make_uint2(*reinterpret_cast<unsigned*>(&lo),
                                                 *reinterpret_cast<unsigned*>(&hi));
            }
        }
    }
}

// gather aggregation + relu + BN-stats fused. 16 nodes/block.
__global__ void __launch_bounds__(288) k_aggregate(float* __restrict__ stats) {
    int tx = threadIdx.x, ty = threadIdx.y;
    int n = blockIdx.x * 16 + ty;     // NN = 3125*16 exact
    int s = g_off[n], e = g_off[n + 1];
    const float4* m4 = (const float4*)g_m;
    float4 acc = ((const float4*)g_agg)[n * HG + tx];
    int j = s;
    for (; j + 3 < e; j += 4) {
        int2 e0 = __ldg(&g_edge[j]);
        int2 e1 = __ldg(&g_edge[j + 1]);
        int2 e2 = __ldg(&g_edge[j + 2]);
        int2 e3 = __ldg(&g_edge[j + 3]);
        float4 v0 = __ldg(&m4[e0.x * HG + tx]);
        float4 v1 = __ldg(&m4[e1.x * HG + tx]);
        float4 v2 = __ldg(&m4[e2.x * HG + tx]);
        float4 v3 = __ldg(&m4[e3.x * HG + tx]);
        fma4(acc, __int_as_float(e0.y), v0);
        fma4(acc, __int_as_float(e1.y), v1);
        fma4(acc, __int_as_float(e2.y), v2);
        fma4(acc, __int_as_float(e3.y), v3);
    }
    for (; j < e; j++) {
        int2 e0 = __ldg(&g_edge[j]);
        fma4(acc, __int_as_float(e0.y), __ldg(&m4[e0.x * HG + tx]));
    }
    acc.x = fmaxf(acc.x, 0.f); acc.y = fmaxf(acc.y, 0.f);
    acc.z = fmaxf(acc.z, 0.f); acc.w = fmaxf(acc.w, 0.f);
    ((float4*)g_h)[n * HG + tx] = acc;

    __shared__ float4 red[2][16][19];
    float4 sq;
    sq.x = acc.x * acc.x; sq.y = acc.y * acc.y;
    sq.z = acc.z * acc.z; sq.w = acc.w * acc.w;
    red[0][ty][tx] = acc;
    red[1][ty][tx] = sq;
    __syncthreads();
    if (ty == 0) {
        float4 S = make_float4(0.f, 0.f, 0.f, 0.f);
        float4 Q = make_float4(0.f, 0.f, 0.f, 0.f);
#pragma unroll
        for (int r = 0; r < 16; r++) {
            float4 a = red[0][r][tx], q = red[1][r][tx];
            S.x += a.x; S.y += a.y; S.z += a.z; S.w += a.w;
            Q.x += q.x; Q.y += q.y; Q.z += q.z; Q.w += q.w;
        }
        atomicAdd(&stats[tx * 4 + 0], S.x);
        atomicAdd(&stats[tx * 4 + 1], S.y);
        atomicAdd(&stats[tx * 4 + 2], S.z);
        atomicAdd(&stats[tx * 4 + 3], S.w);
        atomicAdd(&stats[HID + tx * 4 + 0], Q.x);
        atomicAdd(&stats[HID + tx * 4 + 1], Q.y);
        atomicAdd(&stats[HID + tx * 4 + 2], Q.z);
        atomicAdd(&stats[HID + tx * 4 + 3], Q.w);
    }
}

// fold edge-MLP front-end: C[160][72], bz[72]
__global__ void __launch_bounds__(288) k_fold(const float* __restrict__ W1,
                                              const float* __restrict__ W2,
                                              const float* __restrict__ M1,
                                              const float* __restrict__ b1,
                                              const float* __restrict__ b2,
                                              const float* __restrict__ bm) {
    __shared__ float4 sM1[144 * HG];
    int tid = threadIdx.x;
    const float4* M1_4 = (const float4*)M1;
    for (int i = tid; i < 144 * HG; i += 288) sM1[i] = M1_4[i];
    __syncthreads();
    int rowi = blockIdx.x * 16 + tid / HG;
    int chg = tid % HG;
    if (rowi < 160) {
        float4 acc = make_float4(0.f, 0.f, 0.f, 0.f);
        if (rowi < 144) {
#pragma unroll 8
            for (int k = 0; k < HID; k++)
                fma4(acc, __ldg(&W1[rowi * HID + k]), sM1[k * HG + chg]);
        } else {
            int r2 = rowi - 144;
#pragma unroll
            for (int k = 0; k < HID; k++)
                fma4(acc, __ldg(&W2[r2 * HID + k]), sM1[(HID + k) * HG + chg]);
        }
        ((float4*)g_C)[rowi * HG + chg] = acc;
    }
    if (blockIdx.x == 0 && tid < HG) {
        float4 acc = __ldg(&((const float4*)bm)[tid]);
#pragma unroll 8
        for (int k = 0; k < HID; k++) {
            fma4(acc, __ldg(&b1[k]), sM1[k * HG + tid]);
            fma4(acc, __ldg(&b2[k]), sM1[(HID + k) * HG + tid]);
        }
        ((float4*)g_bz)[tid] = acc;
    }
}

// final per-edge stage: z = U[r] + V[c] + attr@C3 + bz; out = tanh(z).w2 + b2m
__global__ void __launch_bounds__(288, 2) k_edge(const int* __restrict__ row,
                                                 const int* __restrict__ col,
                                                 const float* __restrict__ attr,
                                                 const float* __restrict__ w2,
                                                 const float* __restrict__ b2m,
                                                 float* __restrict__ out) {
    __shared__ float shp[4][288];
    int tid = threadIdx.x;
    int el = tid / HG;          // 0..15
    int chg = tid - el * HG;    // 0..17
    const float4* C3_4 = (const float4*)(g_C + 144 * HID);
    float4 c3[16];
#pragma unroll
    for (int k = 0; k < 16; k++) c3[k] = __ldg(&C3_4[k * HG + chg]);
    float4 bz = __ldg(&((const float4*)g_bz)[chg]);
    float4 wv = __ldg(&((const float4*)w2)[chg]);
    float bout = __ldg(b2m);
    const float4* a4 = (const float4*)attr;
    const int nrounds = NE / 64;   // 12500
    for (int rd = blockIdx.x; rd < nrounds; rd += gridDim.x) {
        int ebase = rd * 64 + el;
#pragma unroll
        for (int s = 0; s < 4; s++) {
            int e = ebase + s * 16;
            int r = __ldg(&row[e]);
            int c = __ldg(&col[e]);
            uint2 up = __ldg(&g_mh[r * HG + chg]);
            uint2 vp = __ldg(&g_aggh[c * HG + chg]);
            float2 ulo = __half22float2(*reinterpret_cast<__half2*>(&up.x));
            float2 uhi = __half22float2(*reinterpret_cast<__half2*>(&up.y));
            float2 vlo = __half22float2(*reinterpret_cast<__half2*>(&vp.x));
            float2 vhi = __half22float2(*reinterpret_cast<__half2*>(&vp.y));
            float4 z;
            z.x = ulo.x + vlo.x + bz.x;
            z.y = ulo.y + vlo.y + bz.y;
            z.z = uhi.x + vhi.x + bz.z;
            z.w = uhi.y + vhi.y + bz.w;
            float4 a0 = __ldg(&a4[e * 4 + 0]);
            float4 a1 = __ldg(&a4[e * 4 + 1]);
            float4 a2 = __ldg(&a4[e * 4 + 2]);
            float4 a3 = __ldg(&a4[e * 4 + 3]);
            fma4(z, a0.x, c3[0]);  fma4(z, a0.y, c3[1]);  fma4(z, a0.z, c3[2]);  fma4(z, a0.w, c3[3]);
            fma4(z, a1.x, c3[4]);  fma4(z, a1.y, c3[5]);  fma4(z, a1.z, c3[6]);  fma4(z, a1.w, c3[7]);
            fma4(z, a2.x, c3[8]);  fma4(z, a2.y, c3[9]);  fma4(z, a2.z, c3[10]); fma4(z, a2.w, c3[11]);
            fma4(z, a3.x, c3[12]); fma4(z, a3.y, c3[13]); fma4(z, a3.z, c3[14]); fma4(z, a3.w, c3[15]);
            shp[s][tid] = tanh_fast(z.x) * wv.x + tanh_fast(z.y) * wv.y +
                          tanh_fast(z.z) * wv.z + tanh_fast(z.w) * wv.w;
        }
        __syncthreads();
        if (tid < 64) {
            int sSel = tid >> 4, e_l = tid & 15;
            float ss = 0.f;
#pragma unroll
            for (int jj = 0; jj < HG; jj++) ss += shp[sSel][e_l * HG + jj];
            out[rd * 64 + tid] = ss + bout;
        }
        __syncthreads();
    }
}

// ---------------- launch ----------------
extern "C" void kernel_launch(void* const* d_in, const int* in_sizes, int n_in,
                              void* d_out, int out_size) {
    const float* x     = (const float*)d_in[0];
    const int*   ei    = (const int*)d_in[1];
    const float* attr  = (const float*)d_in[2];
    const float* nlw   = (const float*)d_in[3];
    const float* nlb   = (const float*)d_in[4];
    const float* convw = (const float*)d_in[5];
    const float* convv = (const float*)d_in[6];
    const float* convb = (const float*)d_in[7];
    const float* gamma = (const float*)d_in[8];
    const float* beta  = (const float*)d_in[9];
    const float* W1    = (const float*)d_in[10];
    const float* b1    = (const float*)d_in[11];
    const float* W2    = (const float*)d_in[12];
    const float* b2e   = (const float*)d_in[13];
    const float* M1    = (const float*)d_in[14];
    const float* bm    = (const float*)d_in[15];
    const float* w2    = (const float*)d_in[16];
    const float* b2m   = (const float*)d_in[17];
    const int* row = ei;
    const int* col = ei + NE;
    float* out = (float*)d_out;

    float* pC = nullptr;
    float* pStats = nullptr;
    cudaGetSymbolAddress((void**)&pC, g_C);
    cudaGetSymbolAddress((void**)&pStats, g_statsL);

    const int GB = (NN + 127) / 128;  // 391 blocks, 128 nodes each

    k_zero<<<(NN + 255) / 256, 256>>>();                                   // 0
    k_deg<<<(NE + 255) / 256, 256>>>(col);                                 // 1
    k_node_lin<<<GB, 288>>>(x, nlw, nlb);                                  // 2
    k_dualgemm<<<GB, 288>>>(convw, convv, convb,                           // 3 (profiled)
                            nullptr, nullptr, nullptr, 0);
    k_scan<<<1, 1024>>>();                                                 // 4
    k_sort<<<(NE + 255) / 256, 256>>>(row, col);                           // 5
    k_aggregate<<<3125, dim3(HG, 16)>>>(pStats);                           // 6
    for (int t = 1; t < NLAY; t++) {
        k_dualgemm<<<GB, 288>>>(convw + t * HID * HID, convv + t * HID * HID,
                                convb + t * HID,
                                gamma + (t - 1) * HID, beta + (t - 1) * HID,
                                pStats + (t - 1) * 2 * HID, 0);
        k_aggregate<<<3125, dim3(HG, 16)>>>(pStats + t * 2 * HID);
    }
    k_fold<<<10, 288>>>(W1, W2, M1, b1, b2e, bm);
    k_dualgemm<<<GB, 288>>>(pC, pC + HID * HID, nullptr,
                            gamma + (NLAY - 1) * HID, beta + (NLAY - 1) * HID,
                            pStats + (NLAY - 1) * 2 * HID, 1);
    k_edge<<<1850, 288>>>(row, col, attr, w2, b2m, out);
}

// round 6
// speedup vs baseline: 1.6275x; 1.1212x over previous
#include <cuda_runtime.h>
#include <cuda_fp16.h>

#define NN   50000
#define NE   800000
#define FIN  128
#define HID  72
#define HG   18      // HID/4
#define NLAY 3

// ---------------- scratch (static __device__, no allocations) ----------------
__device__ int   g_degi[NN];
__device__ float g_dinv[NN];
__device__ int   g_off[NN + 1];
__device__ int   g_cur[NN];
__device__ int2  g_edge[NE];          // {src row, __float_as_int(norm)} CSR-by-col
__device__ float g_h[NN * HID];
__device__ float g_m[NN * HID];
__device__ float g_agg[NN * HID];
__device__ float g_statsL[NLAY][2 * HID];
__device__ float g_C[160 * HID];      // folded weights
__device__ float g_bz[HID];
__device__ uint2 g_mh[NN * HG];       // U as packed half
__device__ uint2 g_aggh[NN * HG];     // V as packed half

// ---------------- helpers ----------------
__device__ __forceinline__ void fma4(float4& a, float s, const float4& b) {
    a.x = __fmaf_rn(s, b.x, a.x);
    a.y = __fmaf_rn(s, b.y, a.y);
    a.z = __fmaf_rn(s, b.z, a.z);
    a.w = __fmaf_rn(s, b.w, a.w);
}
__device__ __forceinline__ float tanh_fast(float x) {
    float e = __expf(2.0f * x);
    return 1.0f - __fdividef(2.0f, e + 1.0f);
}

// ---------------- graph preprocessing ----------------
__global__ void k_zero() {
    int i = blockIdx.x * blockDim.x + threadIdx.x;
    if (i < NN) g_degi[i] = 0;
    if (i < NLAY * 2 * HID) ((float*)g_statsL)[i] = 0.f;
}
__global__ void k_deg(const int* __restrict__ col) {
    int e = blockIdx.x * blockDim.x + threadIdx.x;
    if (e < NE) atomicAdd(&g_degi[col[e]], 1);
}
__global__ void k_scan() {
    __shared__ int sp[1024];
    int tid = threadIdx.x;
    const int CH = (NN + 1023) / 1024;  // 49
    int start = tid * CH;
    int end = min(start + CH, NN);
    int loc = 0;
    for (int i = start; i < end; i++) loc += g_degi[i];
    sp[tid] = loc;
    __syncthreads();
    for (int off = 1; off < 1024; off <<= 1) {
        int v = (tid >= off) ? sp[tid - off] : 0;
        __syncthreads();
        sp[tid] += v;
        __syncthreads();
    }
    int run = sp[tid] - loc;
    for (int i = start; i < end; i++) {
        int d = g_degi[i];
        g_off[i] = run;
        g_cur[i] = run;
        run += d;
        g_dinv[i] = (d > 0) ? rsqrtf((float)d) : 0.0f;
    }
    if (tid == 1023) g_off[NN] = NE;
}
__global__ void k_sort(const int* __restrict__ row, const int* __restrict__ col) {
    int e = blockIdx.x * blockDim.x + threadIdx.x;
    if (e < NE) {
        int r = row[e], c = col[e];
        float nrm = g_dinv[r] * g_dinv[c];
        int p = atomicAdd(&g_cur[c], 1);
        g_edge[p] = make_int2(r, __float_as_int(nrm));
    }
}

// ---------------- node GEMMs (2-D register tiles, x transposed in smem) ----------------
// h = relu(x @ W + b). 96 nodes/block; thread = 3 nodes x 2 f4-cols.
// Block 288 = 9 tx x 32 ty. K chunked 4x32. Grid 521 -> one 592-slot wave @4 blk/SM.
__global__ void __launch_bounds__(288, 4) k_node_lin(const float* __restrict__ x,
                                                     const float* __restrict__ W,
                                                     const float* __restrict__ b) {
    __shared__ float4 sW[32 * HG];       // 9216B
    __shared__ float  sxT[32 * 100];     // 12800B, [k][node], stride 100
    int tid = threadIdx.x;
    int tx = tid % 9, ty = tid / 9;      // ty 0..31
    int n0 = blockIdx.x * 96;
    const float4* W4 = (const float4*)W;
    const float4* x4 = (const float4*)x;
    float4 acc0[3], acc1[3];
    float4 b0 = __ldg(&((const float4*)b)[tx]);
    float4 b1 = __ldg(&((const float4*)b)[tx + 9]);
#pragma unroll
    for (int i = 0; i < 3; i++) { acc0[i] = b0; acc1[i] = b1; }

    for (int c = 0; c < 4; c++) {
        __syncthreads();
        for (int i = tid; i < 32 * HG; i += 288) {
            int kk = i / HG, j = i % HG;
            sW[i] = W4[(c * 32 + kk) * HG + j];
        }
        for (int i = tid; i < 96 * 8; i += 288) {
            int n = i >> 3, kq = i & 7;
            int gn = n0 + n;
            float4 v = make_float4(0.f, 0.f, 0.f, 0.f);
            if (gn < NN) v = x4[gn * 32 + c * 8 + kq];
            sxT[(4 * kq + 0) * 100 + n] = v.x;
            sxT[(4 * kq + 1) * 100 + n] = v.y;
            sxT[(4 * kq + 2) * 100 + n] = v.z;
            sxT[(4 * kq + 3) * 100 + n] = v.w;
        }
        __syncthreads();
#pragma unroll 4
        for (int k = 0; k < 32; k++) {
            float4 w0 = sW[k * HG + tx];
            float4 w1 = sW[k * HG + tx + 9];
            float xv[3];
#pragma unroll
            for (int i = 0; i < 3; i++) xv[i] = sxT[k * 100 + ty * 3 + i];
#pragma unroll
            for (int i = 0; i < 3; i++) {
                fma4(acc0[i], xv[i], w0);
                fma4(acc1[i], xv[i], w1);
            }
        }
    }
    float4* h4 = (float4*)g_h;
#pragma unroll
    for (int i = 0; i < 3; i++) {
        int n = n0 + ty * 3 + i;
        if (n < NN) {
            float4 a = acc0[i];
            a.x = fmaxf(a.x, 0.f); a.y = fmaxf(a.y, 0.f);
            a.z = fmaxf(a.z, 0.f); a.w = fmaxf(a.w, 0.f);
            h4[n * HG + tx] = a;
            a = acc1[i];
            a.x = fmaxf(a.x, 0.f); a.y = fmaxf(a.y, 0.f);
            a.z = fmaxf(a.z, 0.f); a.w = fmaxf(a.w, 0.f);
            h4[n * HG + tx + 9] = a;
        }
    }
}

// [m | agg] = bn(h) @ [Wa | Wb] (+bias on agg half). 96 nodes/block;
// thread = 6 nodes x 2 f4-cols. Block 288 = 18 tx x 16 ty. K chunked 2x36.
__global__ void __launch_bounds__(288, 2) k_dualgemm(const float* __restrict__ Wa,
                                                     const float* __restrict__ Wb,
                                                     const float* __restrict__ bias,
                                                     const float* __restrict__ gamma,
                                                     const float* __restrict__ beta,
                                                     const float* __restrict__ stats,
                                                     int half_out) {
    __shared__ float4 sW[36 * 36];       // 20736B: [k][j<18: Wa, j>=18: Wb]
    __shared__ float  sxT[36 * 100];     // 14400B: [k][node], stride 100
    __shared__ float  s_scale[HID], s_shift[HID];
    int tid = threadIdx.x;
    int tx = tid % HG, ty = tid / HG;    // ty 0..15
    int n0 = blockIdx.x * 96;
    const float4* Wa4 = (const float4*)Wa;
    const float4* Wb4 = (const float4*)Wb;
    const float4* h4 = (const float4*)g_h;
    const int use_bn = (gamma != nullptr);

    if (use_bn && tid < HID) {
        float S = __ldg(&stats[tid]), Q = __ldg(&stats[HID + tid]);
        float mu = S * (1.0f / NN);
        float var = Q * (1.0f / NN) - mu * mu;
        float sc = __ldg(&gamma[tid]) * rsqrtf(var + 1e-5f);
        s_scale[tid] = sc;
        s_shift[tid] = __ldg(&beta[tid]) - mu * sc;
    }

    float4 acc0[6], acc1[6];
    float4 b1 = (bias != nullptr) ? __ldg(&((const float4*)bias)[tx])
                                  : make_float4(0.f, 0.f, 0.f, 0.f);
#pragma unroll
    for (int i = 0; i < 6; i++) {
        acc0[i] = make_float4(0.f, 0.f, 0.f, 0.f);
        acc1[i] = b1;
    }

    for (int c = 0; c < 2; c++) {
        __syncthreads();   // first iteration also publishes s_scale/s_shift
        for (int i = tid; i < 36 * 36; i += 288) {
            int kk = i / 36, j = i % 36;
            sW[i] = (j < HG) ? Wa4[(c * 36 + kk) * HG + j]
                             : Wb4[(c * 36 + kk) * HG + j - HG];
        }
        for (int i = tid; i < 96 * 9; i += 288) {  // exactly 3 iters
            int n = i / 9, kq = i % 9;
            int gn = n0 + n;
            float4 v = make_float4(0.f, 0.f, 0.f, 0.f);
            if (gn < NN) {
                v = h4[gn * HG + c * 9 + kq];
                if (use_bn) {
                    int k0 = (c * 9 + kq) * 4;
                    v.x = __fmaf_rn(v.x, s_scale[k0 + 0], s_shift[k0 + 0]);
                    v.y = __fmaf_rn(v.y, s_scale[k0 + 1], s_shift[k0 + 1]);
                    v.z = __fmaf_rn(v.z, s_scale[k0 + 2], s_shift[k0 + 2]);
                    v.w = __fmaf_rn(v.w, s_scale[k0 + 3], s_shift[k0 + 3]);
                }
            }
            sxT[(4 * kq + 0) * 100 + n] = v.x;
            sxT[(4 * kq + 1) * 100 + n] = v.y;
            sxT[(4 * kq + 2) * 100 + n] = v.z;
            sxT[(4 * kq + 3) * 100 + n] = v.w;
        }
        __syncthreads();
#pragma unroll 4
        for (int k = 0; k < 36; k++) {
            float4 w0 = sW[k * 36 + tx];
            float4 w1 = sW[k * 36 + 18 + tx];
            float2 p0 = *(const float2*)&sxT[k * 100 + ty * 6 + 0];
            float2 p1 = *(const float2*)&sxT[k * 100 + ty * 6 + 2];
            float2 p2 = *(const float2*)&sxT[k * 100 + ty * 6 + 4];
            float xv[6] = {p0.x, p0.y, p1.x, p1.y, p2.x, p2.y};
#pragma unroll
            for (int i = 0; i < 6; i++) {
                fma4(acc0[i], xv[i], w0);
                fma4(acc1[i], xv[i], w1);
            }
        }
    }
    if (!half_out) {
        float4* m4 = (float4*)g_m;
        float4* agg4 = (float4*)g_agg;
#pragma unroll
        for (int i = 0; i < 6; i++) {
            int n = n0 + ty * 6 + i;
            if (n < NN) {
                m4[n * HG + tx] = acc0[i];
                agg4[n * HG + tx] = acc1[i];
            }
        }
    } else {
#pragma unroll
        for (int i = 0; i < 6; i++) {
            int n = n0 + ty * 6 + i;
            if (n < NN) {
                __half2 lo = __floats2half2_rn(acc0[i].x, acc0[i].y);
                __half2 hi = __floats2half2_rn(acc0[i].z, acc0[i].w);
                g_mh[n * HG + tx] = make_uint2(*reinterpret_cast<unsigned*>(&lo),
                                               *reinterpret_cast<unsigned*>(&hi));
                lo = __floats2half2_rn(acc1[i].x, acc1[i].y);
                hi = __floats2half2_rn(acc1[i].z, acc1[i].w);
                g_aggh[n * HG + tx] = make_uint2(*reinterpret_cast<unsigned*>(&lo),
                                                 *reinterpret_cast<unsigned*>(&hi));
            }
        }
    }
}

// gather aggregation + relu + BN-stats fused. 16 nodes/block.
__global__ void __launch_bounds__(288) k_aggregate(float* __restrict__ stats) {
    int tx = threadIdx.x, ty = threadIdx.y;
    int n = blockIdx.x * 16 + ty;     // NN = 3125*16 exact
    int s = g_off[n], e = g_off[n + 1];
    const float4* m4 = (const float4*)g_m;
    float4 acc = ((const float4*)g_agg)[n * HG + tx];
    int j = s;
    for (; j + 3 < e; j += 4) {
        int2 e0 = __ldg(&g_edge[j]);
        int2 e1 = __ldg(&g_edge[j + 1]);
        int2 e2 = __ldg(&g_edge[j + 2]);
        int2 e3 = __ldg(&g_edge[j + 3]);
        float4 v0 = __ldg(&m4[e0.x * HG + tx]);
        float4 v1 = __ldg(&m4[e1.x * HG + tx]);
        float4 v2 = __ldg(&m4[e2.x * HG + tx]);
        float4 v3 = __ldg(&m4[e3.x * HG + tx]);
        fma4(acc, __int_as_float(e0.y), v0);
        fma4(acc, __int_as_float(e1.y), v1);
        fma4(acc, __int_as_float(e2.y), v2);
        fma4(acc, __int_as_float(e3.y), v3);
    }
    for (; j < e; j++) {
        int2 e0 = __ldg(&g_edge[j]);
        fma4(acc, __int_as_float(e0.y), __ldg(&m4[e0.x * HG + tx]));
    }
    acc.x = fmaxf(acc.x, 0.f); acc.y = fmaxf(acc.y, 0.f);
    acc.z = fmaxf(acc.z, 0.f); acc.w = fmaxf(acc.w, 0.f);
    ((float4*)g_h)[n * HG + tx] = acc;

    __shared__ float4 red[2][16][19];
    float4 sq;
    sq.x = acc.x * acc.x; sq.y = acc.y * acc.y;
    sq.z = acc.z * acc.z; sq.w = acc.w * acc.w;
    red[0][ty][tx] = acc;
    red[1][ty][tx] = sq;
    __syncthreads();
    if (ty == 0) {
        float4 S = make_float4(0.f, 0.f, 0.f, 0.f);
        float4 Q = make_float4(0.f, 0.f, 0.f, 0.f);
#pragma unroll
        for (int r = 0; r < 16; r++) {
            float4 a = red[0][r][tx], q = red[1][r][tx];
            S.x += a.x; S.y += a.y; S.z += a.z; S.w += a.w;
            Q.x += q.x; Q.y += q.y; Q.z += q.z; Q.w += q.w;
        }
        atomicAdd(&stats[tx * 4 + 0], S.x);
        atomicAdd(&stats[tx * 4 + 1], S.y);
        atomicAdd(&stats[tx * 4 + 2], S.z);
        atomicAdd(&stats[tx * 4 + 3], S.w);
        atomicAdd(&stats[HID + tx * 4 + 0], Q.x);
        atomicAdd(&stats[HID + tx * 4 + 1], Q.y);
        atomicAdd(&stats[HID + tx * 4 + 2], Q.z);
        atomicAdd(&stats[HID + tx * 4 + 3], Q.w);
    }
}

// fold edge-MLP front-end: C[160][72], bz[72]
__global__ void __launch_bounds__(288) k_fold(const float* __restrict__ W1,
                                              const float* __restrict__ W2,
                                              const float* __restrict__ M1,
                                              const float* __restrict__ b1,
                                              const float* __restrict__ b2,
                                              const float* __restrict__ bm) {
    __shared__ float4 sM1[144 * HG];
    int tid = threadIdx.x;
    const float4* M1_4 = (const float4*)M1;
    for (int i = tid; i < 144 * HG; i += 288) sM1[i] = M1_4[i];
    __syncthreads();
    int rowi = blockIdx.x * 16 + tid / HG;
    int chg = tid % HG;
    if (rowi < 160) {
        float4 acc = make_float4(0.f, 0.f, 0.f, 0.f);
        if (rowi < 144) {
#pragma unroll 8
            for (int k = 0; k < HID; k++)
                fma4(acc, __ldg(&W1[rowi * HID + k]), sM1[k * HG + chg]);
        } else {
            int r2 = rowi - 144;
#pragma unroll
            for (int k = 0; k < HID; k++)
                fma4(acc, __ldg(&W2[r2 * HID + k]), sM1[(HID + k) * HG + chg]);
        }
        ((float4*)g_C)[rowi * HG + chg] = acc;
    }
    if (blockIdx.x == 0 && tid < HG) {
        float4 acc = __ldg(&((const float4*)bm)[tid]);
#pragma unroll 8
        for (int k = 0; k < HID; k++) {
            fma4(acc, __ldg(&b1[k]), sM1[k * HG + tid]);
            fma4(acc, __ldg(&b2[k]), sM1[(HID + k) * HG + tid]);
        }
        ((float4*)g_bz)[tid] = acc;
    }
}

// final per-edge stage: z = U[r] + V[c] + attr@C3 + bz; out = tanh(z).w2 + b2m
// attr@C3 done in half2 (HFMA2, 2 MAC/lane); U/V fp16-packed.
__global__ void __launch_bounds__(288, 3) k_edge(const int* __restrict__ row,
                                                 const int* __restrict__ col,
                                                 const float* __restrict__ attr,
                                                 const float* __restrict__ w2,
                                                 const float* __restrict__ b2m,
                                                 float* __restrict__ out) {
    __shared__ float shp[4][288];
    int tid = threadIdx.x;
    int el = tid / HG;          // 0..15
    int chg = tid - el * HG;    // 0..17
    const float4* C3_4 = (const float4*)(g_C + 144 * HID);
    __half2 c3l[16], c3h[16];
#pragma unroll
    for (int k = 0; k < 16; k++) {
        float4 t = __ldg(&C3_4[k * HG + chg]);
        c3l[k] = __floats2half2_rn(t.x, t.y);
        c3h[k] = __floats2half2_rn(t.z, t.w);
    }
    float4 bz = __ldg(&((const float4*)g_bz)[chg]);
    float4 wv = __ldg(&((const float4*)w2)[chg]);
    float bout = __ldg(b2m);
    const float4* a4 = (const float4*)attr;
    const int nrounds = NE / 64;   // 12500
    for (int rd = blockIdx.x; rd < nrounds; rd += gridDim.x) {
        int ebase = rd * 64 + el;
#pragma unroll
        for (int s = 0; s < 4; s++) {
            int e = ebase + s * 16;
            int r = __ldg(&row[e]);
            int c = __ldg(&col[e]);
            uint2 up = __ldg(&g_mh[r * HG + chg]);
            uint2 vp = __ldg(&g_aggh[c * HG + chg]);
            float2 ulo = __half22float2(*reinterpret_cast<__half2*>(&up.x));
            float2 uhi = __half22float2(*reinterpret_cast<__half2*>(&up.y));
            float2 vlo = __half22float2(*reinterpret_cast<__half2*>(&vp.x));
            float2 vhi = __half22float2(*reinterpret_cast<__half2*>(&vp.y));
            float4 a0 = __ldg(&a4[e * 4 + 0]);
            float4 a1 = __ldg(&a4[e * 4 + 1]);
            float4 a2 = __ldg(&a4[e * 4 + 2]);
            float4 a3 = __ldg(&a4[e * 4 + 3]);
            __half2 accl = __float2half2_rn(0.f);
            __half2 acch = __float2half2_rn(0.f);
            float av[16] = {a0.x, a0.y, a0.z, a0.w, a1.x, a1.y, a1.z, a1.w,
                            a2.x, a2.y, a2.z, a2.w, a3.x, a3.y, a3.z, a3.w};
#pragma unroll
            for (int k = 0; k < 16; k++) {
                __half2 ah = __float2half2_rn(av[k]);
                accl = __hfma2(ah, c3l[k], accl);
                acch = __hfma2(ah, c3h[k], acch);
            }
            float2 fl = __half22float2(accl);
            float2 fh = __half22float2(acch);
            float4 z;
            z.x = ulo.x + vlo.x + bz.x + fl.x;
            z.y = ulo.y + vlo.y + bz.y + fl.y;
            z.z = uhi.x + vhi.x + bz.z + fh.x;
            z.w = uhi.y + vhi.y + bz.w + fh.y;
            shp[s][tid] = tanh_fast(z.x) * wv.x + tanh_fast(z.y) * wv.y +
                          tanh_fast(z.z) * wv.z + tanh_fast(z.w) * wv.w;
        }
        __syncthreads();
        if (tid < 64) {
            int sSel = tid >> 4, e_l = tid & 15;
            float ss = 0.f;
#pragma unroll
            for (int jj = 0; jj < HG; jj++) ss += shp[sSel][e_l * HG + jj];
            out[rd * 64 + tid] = ss + bout;
        }
        __syncthreads();
    }
}

// ---------------- launch ----------------
extern "C" void kernel_launch(void* const* d_in, const int* in_sizes, int n_in,
                              void* d_out, int out_size) {
    const float* x     = (const float*)d_in[0];
    const int*   ei    = (const int*)d_in[1];
    const float* attr  = (const float*)d_in[2];
    const float* nlw   = (const float*)d_in[3];
    const float* nlb   = (const float*)d_in[4];
    const float* convw = (const float*)d_in[5];
    const float* convv = (const float*)d_in[6];
    const float* convb = (const float*)d_in[7];
    const float* gamma = (const float*)d_in[8];
    const float* beta  = (const float*)d_in[9];
    const float* W1    = (const float*)d_in[10];
    const float* b1    = (const float*)d_in[11];
    const float* W2    = (const float*)d_in[12];
    const float* b2e   = (const float*)d_in[13];
    const float* M1    = (const float*)d_in[14];
    const float* bm    = (const float*)d_in[15];
    const float* w2    = (const float*)d_in[16];
    const float* b2m   = (const float*)d_in[17];
    const int* row = ei;
    const int* col = ei + NE;
    float* out = (float*)d_out;

    float* pC = nullptr;
    float* pStats = nullptr;
    cudaGetSymbolAddress((void**)&pC, g_C);
    cudaGetSymbolAddress((void**)&pStats, g_statsL);

    const int GB = (NN + 95) / 96;  // 521 blocks, 96 nodes each

    k_zero<<<(NN + 255) / 256, 256>>>();                                   // 0
    k_deg<<<(NE + 255) / 256, 256>>>(col);                                 // 1
    k_node_lin<<<GB, 288>>>(x, nlw, nlb);                                  // 2
    k_dualgemm<<<GB, 288>>>(convw, convv, convb,                           // 3 (profiled)
                            nullptr, nullptr, nullptr, 0);
    k_scan<<<1, 1024>>>();                                                 // 4
    k_sort<<<(NE + 255) / 256, 256>>>(row, col);                           // 5
    k_aggregate<<<3125, dim3(HG, 16)>>>(pStats);                           // 6
    for (int t = 1; t < NLAY; t++) {
        k_dualgemm<<<GB, 288>>>(convw + t * HID * HID, convv + t * HID * HID,
                                convb + t * HID,
                                gamma + (t - 1) * HID, beta + (t - 1) * HID,
                                pStats + (t - 1) * 2 * HID, 0);
        k_aggregate<<<3125, dim3(HG, 16)>>>(pStats + t * 2 * HID);
    }
    k_fold<<<10, 288>>>(W1, W2, M1, b1, b2e, bm);
    k_dualgemm<<<GB, 288>>>(pC, pC + HID * HID, nullptr,
                            gamma + (NLAY - 1) * HID, beta + (NLAY - 1) * HID,
                            pStats + (NLAY - 1) * 2 * HID, 1);
    k_edge<<<1850, 288>>>(row, col, attr, w2, b2m, out);
}

// round 7
// speedup vs baseline: 1.7250x; 1.0600x over previous
#include <cuda_runtime.h>
#include <cuda_fp16.h>

#define NN   50000
#define NNP  50048          // padded to 128
#define NE   800000
#define FIN  128
#define HID  72
#define HG   18             // HID/4
#define NLAY 3

// ---------------- scratch (static __device__, no allocations) ----------------
__device__ int      g_degi[NN];
__device__ float    g_dinv[NN];
__device__ int      g_off[NN + 1];
__device__ int      g_cur[NN];
__device__ int2     g_edge[NE];        // {src row, __float_as_int(norm)} CSR-by-col
__device__ unsigned g_h16[NNP * 40];   // h as fp16, rows padded to 80 halves (40 u32)
__device__ float    g_m[NN * HID];
__device__ float    g_agg[NN * HID];
__device__ float    g_statsL[NLAY][2 * HID];
__device__ float    g_C[160 * HID];    // folded edge-MLP weights (fp32)
__device__ float    g_bz[HID];
__device__ __half   g_wt[4][144 * 80]; // BN-folded fp16 weights, [col][k] (k padded 80)
__device__ float    g_biasF[4][144];   // BN-folded biases
__device__ uint2    g_mh[NN * HG];     // U packed half
__device__ uint2    g_aggh[NN * HG];   // V packed half

// ---------------- helpers ----------------
__device__ __forceinline__ void fma4(float4& a, float s, const float4& b) {
    a.x = __fmaf_rn(s, b.x, a.x);
    a.y = __fmaf_rn(s, b.y, a.y);
    a.z = __fmaf_rn(s, b.z, a.z);
    a.w = __fmaf_rn(s, b.w, a.w);
}
__device__ __forceinline__ float tanh_fast(float x) {
    float e = __expf(2.0f * x);
    return 1.0f - __fdividef(2.0f, e + 1.0f);
}
__device__ __forceinline__ void mma16816(float* c, const unsigned* a,
                                         unsigned b0, unsigned b1) {
    asm volatile(
        "mma.sync.aligned.m16n8k16.row.col.f32.f16.f16.f32 "
        "{%0,%1,%2,%3}, {%4,%5,%6,%7}, {%8,%9}, {%0,%1,%2,%3};"
        : "+f"(c[0]), "+f"(c[1]), "+f"(c[2]), "+f"(c[3])
        : "r"(a[0]), "r"(a[1]), "r"(a[2]), "r"(a[3]), "r"(b0), "r"(b1));
}

// ---------------- graph preprocessing ----------------
__global__ void k_zero() {
    int i = blockIdx.x * blockDim.x + threadIdx.x;
    if (i < NN) g_degi[i] = 0;
    if (i < NLAY * 2 * HID) ((float*)g_statsL)[i] = 0.f;
}
__global__ void k_deg(const int* __restrict__ col) {
    int e = blockIdx.x * blockDim.x + threadIdx.x;
    if (e < NE) atomicAdd(&g_degi[col[e]], 1);
}
__global__ void k_scan() {
    __shared__ int sp[1024];
    int tid = threadIdx.x;
    const int CH = (NN + 1023) / 1024;  // 49
    int start = tid * CH;
    int end = min(start + CH, NN);
    int loc = 0;
    for (int i = start; i < end; i++) loc += g_degi[i];
    sp[tid] = loc;
    __syncthreads();
    for (int off = 1; off < 1024; off <<= 1) {
        int v = (tid >= off) ? sp[tid - off] : 0;
        __syncthreads();
        sp[tid] += v;
        __syncthreads();
    }
    int run = sp[tid] - loc;
    for (int i = start; i < end; i++) {
        int d = g_degi[i];
        g_off[i] = run;
        g_cur[i] = run;
        run += d;
        g_dinv[i] = (d > 0) ? rsqrtf((float)d) : 0.0f;
    }
    if (tid == 1023) g_off[NN] = NE;
}
__global__ void k_sort(const int* __restrict__ row, const int* __restrict__ col) {
    int e = blockIdx.x * blockDim.x + threadIdx.x;
    if (e < NE) {
        int r = row[e], c = col[e];
        float nrm = g_dinv[r] * g_dinv[c];
        int p = atomicAdd(&g_cur[c], 1);
        g_edge[p] = make_int2(r, __float_as_int(nrm));
    }
}

// ---------------- weight prep: fold BN into fp16 weights + bias ----------------
// wt[j][k] = scale[k]*W[k][j] (fp16, k padded to 80 with zeros)
// biasOut[j] = (base bias) + sum_k shift[k]*W[k][j]
__global__ void k_prep(const float* __restrict__ Wa, const float* __restrict__ Wb,
                       const float* __restrict__ bias_b,
                       const float* __restrict__ gamma, const float* __restrict__ beta,
                       const float* __restrict__ stats,
                       __half* __restrict__ wt, float* __restrict__ biasOut) {
    __shared__ float sc[HID], sh[HID];
    int tid = threadIdx.x;   // 160 threads
    if (tid < HID) {
        if (gamma != nullptr) {
            float S = __ldg(&stats[tid]), Q = __ldg(&stats[HID + tid]);
            float mu = S * (1.0f / NN);
            float var = Q * (1.0f / NN) - mu * mu;
            float s = __ldg(&gamma[tid]) * rsqrtf(var + 1e-5f);
            sc[tid] = s;
            sh[tid] = __ldg(&beta[tid]) - mu * s;
        } else {
            sc[tid] = 1.0f;
            sh[tid] = 0.0f;
        }
    }
    __syncthreads();
    if (tid < 144) {
        const float* Wsrc = (tid < HID) ? Wa : Wb;
        int j = (tid < HID) ? tid : tid - HID;
        float bm = (bias_b != nullptr && tid >= HID) ? __ldg(&bias_b[j]) : 0.0f;
        for (int k = 0; k < HID; k++) {
            float w = __ldg(&Wsrc[k * HID + j]);
            wt[tid * 80 + k] = __float2half(sc[k] * w);
            bm = __fmaf_rn(sh[k], w, bm);
        }
        for (int k = HID; k < 80; k++) wt[tid * 80 + k] = __float2half(0.0f);
        biasOut[tid] = bm;
    }
}

// ---------------- node_lin (FFMA, writes fp16 h) ----------------
// h16 = relu(x @ W + b). 96 nodes/block; thread = 3 nodes x 2 f4-cols.
__global__ void __launch_bounds__(288, 4) k_node_lin(const float* __restrict__ x,
                                                     const float* __restrict__ W,
                                                     const float* __restrict__ b) {
    __shared__ float4 sW[32 * HG];
    __shared__ float  sxT[32 * 100];
    int tid = threadIdx.x;
    int tx = tid % 9, ty = tid / 9;      // ty 0..31
    int n0 = blockIdx.x * 96;
    const float4* W4 = (const float4*)W;
    const float4* x4 = (const float4*)x;
    float4 acc0[3], acc1[3];
    float4 b0 = __ldg(&((const float4*)b)[tx]);
    float4 b1 = __ldg(&((const float4*)b)[tx + 9]);
#pragma unroll
    for (int i = 0; i < 3; i++) { acc0[i] = b0; acc1[i] = b1; }

    for (int c = 0; c < 4; c++) {
        __syncthreads();
        for (int i = tid; i < 32 * HG; i += 288) {
            int kk = i / HG, j = i % HG;
            sW[i] = W4[(c * 32 + kk) * HG + j];
        }
        for (int i = tid; i < 96 * 8; i += 288) {
            int n = i >> 3, kq = i & 7;
            int gn = n0 + n;
            float4 v = make_float4(0.f, 0.f, 0.f, 0.f);
            if (gn < NN) v = x4[gn * 32 + c * 8 + kq];
            sxT[(4 * kq + 0) * 100 + n] = v.x;
            sxT[(4 * kq + 1) * 100 + n] = v.y;
            sxT[(4 * kq + 2) * 100 + n] = v.z;
            sxT[(4 * kq + 3) * 100 + n] = v.w;
        }
        __syncthreads();
#pragma unroll 4
        for (int k = 0; k < 32; k++) {
            float4 w0 = sW[k * HG + tx];
            float4 w1 = sW[k * HG + tx + 9];
            float xv[3];
#pragma unroll
            for (int i = 0; i < 3; i++) xv[i] = sxT[k * 100 + ty * 3 + i];
#pragma unroll
            for (int i = 0; i < 3; i++) {
                fma4(acc0[i], xv[i], w0);
                fma4(acc1[i], xv[i], w1);
            }
        }
    }
#pragma unroll
    for (int i = 0; i < 3; i++) {
        int n = n0 + ty * 3 + i;
        if (n < NN) {
            float4 a = acc0[i];
            a.x = fmaxf(a.x, 0.f); a.y = fmaxf(a.y, 0.f);
            a.z = fmaxf(a.z, 0.f); a.w = fmaxf(a.w, 0.f);
            __half2 lo = __floats2half2_rn(a.x, a.y);
            __half2 hi = __floats2half2_rn(a.z, a.w);
            ((uint2*)g_h16)[n * 20 + tx] = make_uint2(
                *reinterpret_cast<unsigned*>(&lo), *reinterpret_cast<unsigned*>(&hi));
            a = acc1[i];
            a.x = fmaxf(a.x, 0.f); a.y = fmaxf(a.y, 0.f);
            a.z = fmaxf(a.z, 0.f); a.w = fmaxf(a.w, 0.f);
            lo = __floats2half2_rn(a.x, a.y);
            hi = __floats2half2_rn(a.z, a.w);
            ((uint2*)g_h16)[n * 20 + tx + 9] = make_uint2(
                *reinterpret_cast<unsigned*>(&lo), *reinterpret_cast<unsigned*>(&hi));
            if (tx < 4) g_h16[n * 40 + 36 + tx] = 0u;   // zero pad cols 72..79
            if (tx < 2) ((uint2*)g_h16)[n * 20 + 18 + tx] = make_uint2(0u, 0u); // redundant-safe
        }
    }
}

// ---------------- tensor-core dual GEMM: [m|agg] = h16 @ wt + bias ----------------
// 128 nodes/block, 256 threads = 8 warps (4 along M x 2 along N-halves).
// No smem, no syncs: fragments LDG'd directly (h16 from L2, wt L1-resident).
__global__ void __launch_bounds__(256, 2) k_dualgemm_tc(const __half* __restrict__ wt,
                                                        const float* __restrict__ bias,
                                                        int half_out) {
    int wid = threadIdx.x >> 5, lane = threadIdx.x & 31;
    int g = lane >> 2, t = lane & 3;
    int warpM = wid >> 1, warpN = wid & 1;
    int n0 = blockIdx.x * 128 + warpM * 32;
    const unsigned* h32 = g_h16;                         // row stride 40 u32
    const unsigned* w32 = (const unsigned*)wt;           // col stride 40 u32

    float acc[2][9][4];
#pragma unroll
    for (int fr = 0; fr < 2; fr++)
#pragma unroll
        for (int f = 0; f < 9; f++)
#pragma unroll
            for (int q = 0; q < 4; q++) acc[fr][f][q] = 0.0f;

    const unsigned* wbase = w32 + (size_t)(warpN * 72 + g) * 40 + t;
    const unsigned* hbase = h32 + (size_t)(n0 + g) * 40 + t;

#pragma unroll
    for (int kc = 0; kc < 5; kc++) {
        int kb = kc * 8;  // u32 offset within row
        unsigned a[2][4];
#pragma unroll
        for (int fr = 0; fr < 2; fr++) {
            const unsigned* hp = hbase + fr * (16 * 40) + kb;
            a[fr][0] = __ldg(hp);
            a[fr][2] = __ldg(hp + 4);
            a[fr][1] = __ldg(hp + 8 * 40);
            a[fr][3] = __ldg(hp + 8 * 40 + 4);
        }
#pragma unroll
        for (int f = 0; f < 9; f++) {
            const unsigned* wp = wbase + f * (8 * 40) + kb;
            unsigned b0 = __ldg(wp);
            unsigned b1 = __ldg(wp + 4);
            mma16816(acc[0][f], a[0], b0, b1);
            mma16816(acc[1][f], a[1], b0, b1);
        }
    }

#pragma unroll
    for (int fr = 0; fr < 2; fr++) {
        int r0 = n0 + fr * 16 + g;
#pragma unroll
        for (int f = 0; f < 9; f++) {
            int colg = warpN * 72 + f * 8 + 2 * t;
            float2 bv = *(const float2*)&bias[colg];
            int lcol = f * 8 + 2 * t;
            float d0 = acc[fr][f][0] + bv.x, d1 = acc[fr][f][1] + bv.y;
            float d2 = acc[fr][f][2] + bv.x, d3 = acc[fr][f][3] + bv.y;
            if (!half_out) {
                float* outp = warpN ? g_agg : g_m;
                if (r0 < NN) *(float2*)&outp[r0 * HID + lcol] = make_float2(d0, d1);
                if (r0 + 8 < NN) *(float2*)&outp[(r0 + 8) * HID + lcol] = make_float2(d2, d3);
            } else {
                unsigned* outp = warpN ? (unsigned*)g_aggh : (unsigned*)g_mh;
                if (r0 < NN) {
                    __half2 p = __floats2half2_rn(d0, d1);
                    outp[r0 * 36 + (lcol >> 1)] = *reinterpret_cast<unsigned*>(&p);
                }
                if (r0 + 8 < NN) {
                    __half2 p = __floats2half2_rn(d2, d3);
                    outp[(r0 + 8) * 36 + (lcol >> 1)] = *reinterpret_cast<unsigned*>(&p);
                }
            }
        }
    }
}

// gather aggregation + relu + BN-stats fused. 16 nodes/block. Writes fp16 h.
__global__ void __launch_bounds__(288) k_aggregate(float* __restrict__ stats) {
    int tx = threadIdx.x, ty = threadIdx.y;
    int n = blockIdx.x * 16 + ty;     // NN = 3125*16 exact
    int s = g_off[n], e = g_off[n + 1];
    const float4* m4 = (const float4*)g_m;
    float4 acc = ((const float4*)g_agg)[n * HG + tx];
    int j = s;
    for (; j + 3 < e; j += 4) {
        int2 e0 = __ldg(&g_edge[j]);
        int2 e1 = __ldg(&g_edge[j + 1]);
        int2 e2 = __ldg(&g_edge[j + 2]);
        int2 e3 = __ldg(&g_edge[j + 3]);
        float4 v0 = __ldg(&m4[e0.x * HG + tx]);
        float4 v1 = __ldg(&m4[e1.x * HG + tx]);
        float4 v2 = __ldg(&m4[e2.x * HG + tx]);
        float4 v3 = __ldg(&m4[e3.x * HG + tx]);
        fma4(acc, __int_as_float(e0.y), v0);
        fma4(acc, __int_as_float(e1.y), v1);
        fma4(acc, __int_as_float(e2.y), v2);
        fma4(acc, __int_as_float(e3.y), v3);
    }
    for (; j < e; j++) {
        int2 e0 = __ldg(&g_edge[j]);
        fma4(acc, __int_as_float(e0.y), __ldg(&m4[e0.x * HG + tx]));
    }
    acc.x = fmaxf(acc.x, 0.f); acc.y = fmaxf(acc.y, 0.f);
    acc.z = fmaxf(acc.z, 0.f); acc.w = fmaxf(acc.w, 0.f);
    {
        __half2 lo = __floats2half2_rn(acc.x, acc.y);
        __half2 hi = __floats2half2_rn(acc.z, acc.w);
        ((uint2*)g_h16)[n * 20 + tx] = make_uint2(
            *reinterpret_cast<unsigned*>(&lo), *reinterpret_cast<unsigned*>(&hi));
        if (tx < 4) g_h16[n * 40 + 36 + tx] = 0u;
    }

    __shared__ float4 red[2][16][19];
    float4 sq;
    sq.x = acc.x * acc.x; sq.y = acc.y * acc.y;
    sq.z = acc.z * acc.z; sq.w = acc.w * acc.w;
    red[0][ty][tx] = acc;
    red[1][ty][tx] = sq;
    __syncthreads();
    if (ty == 0) {
        float4 S = make_float4(0.f, 0.f, 0.f, 0.f);
        float4 Q = make_float4(0.f, 0.f, 0.f, 0.f);
#pragma unroll
        for (int r = 0; r < 16; r++) {
            float4 a = red[0][r][tx], q = red[1][r][tx];
            S.x += a.x; S.y += a.y; S.z += a.z; S.w += a.w;
            Q.x += q.x; Q.y += q.y; Q.z += q.z; Q.w += q.w;
        }
        atomicAdd(&stats[tx * 4 + 0], S.x);
        atomicAdd(&stats[tx * 4 + 1], S.y);
        atomicAdd(&stats[tx * 4 + 2], S.z);
        atomicAdd(&stats[tx * 4 + 3], S.w);
        atomicAdd(&stats[HID + tx * 4 + 0], Q.x);
        atomicAdd(&stats[HID + tx * 4 + 1], Q.y);
        atomicAdd(&stats[HID + tx * 4 + 2], Q.z);
        atomicAdd(&stats[HID + tx * 4 + 3], Q.w);
    }
}

// fold edge-MLP front-end: C[160][72], bz[72]
__global__ void __launch_bounds__(288) k_fold(const float* __restrict__ W1,
                                              const float* __restrict__ W2,
                                              const float* __restrict__ M1,
                                              const float* __restrict__ b1,
                                              const float* __restrict__ b2,
                                              const float* __restrict__ bm) {
    __shared__ float4 sM1[144 * HG];
    int tid = threadIdx.x;
    const float4* M1_4 = (const float4*)M1;
    for (int i = tid; i < 144 * HG; i += 288) sM1[i] = M1_4[i];
    __syncthreads();
    int rowi = blockIdx.x * 16 + tid / HG;
    int chg = tid % HG;
    if (rowi < 160) {
        float4 acc = make_float4(0.f, 0.f, 0.f, 0.f);
        if (rowi < 144) {
#pragma unroll 8
            for (int k = 0; k < HID; k++)
                fma4(acc, __ldg(&W1[rowi * HID + k]), sM1[k * HG + chg]);
        } else {
            int r2 = rowi - 144;
#pragma unroll
            for (int k = 0; k < HID; k++)
                fma4(acc, __ldg(&W2[r2 * HID + k]), sM1[(HID + k) * HG + chg]);
        }
        ((float4*)g_C)[rowi * HG + chg] = acc;
    }
    if (blockIdx.x == 0 && tid < HG) {
        float4 acc = __ldg(&((const float4*)bm)[tid]);
#pragma unroll 8
        for (int k = 0; k < HID; k++) {
            fma4(acc, __ldg(&b1[k]), sM1[k * HG + tid]);
            fma4(acc, __ldg(&b2[k]), sM1[(HID + k) * HG + tid]);
        }
        ((float4*)g_bz)[tid] = acc;
    }
}

// final per-edge stage: z = U[r] + V[c] + attr@C3 + bz; out = tanh(z).w2 + b2m
__global__ void __launch_bounds__(288, 3) k_edge(const int* __restrict__ row,
                                                 const int* __restrict__ col,
                                                 const float* __restrict__ attr,
                                                 const float* __restrict__ w2,
                                                 const float* __restrict__ b2m,
                                                 float* __restrict__ out) {
    __shared__ float shp[4][288];
    int tid = threadIdx.x;
    int el = tid / HG;          // 0..15
    int chg = tid - el * HG;    // 0..17
    const float4* C3_4 = (const float4*)(g_C + 144 * HID);
    __half2 c3l[16], c3h[16];
#pragma unroll
    for (int k = 0; k < 16; k++) {
        float4 tt = __ldg(&C3_4[k * HG + chg]);
        c3l[k] = __floats2half2_rn(tt.x, tt.y);
        c3h[k] = __floats2half2_rn(tt.z, tt.w);
    }
    float4 bz = __ldg(&((const float4*)g_bz)[chg]);
    float4 wv = __ldg(&((const float4*)w2)[chg]);
    float bout = __ldg(b2m);
    const float4* a4 = (const float4*)attr;
    const int nrounds = NE / 64;   // 12500
    for (int rd = blockIdx.x; rd < nrounds; rd += gridDim.x) {
        int ebase = rd * 64 + el;
#pragma unroll
        for (int s = 0; s < 4; s++) {
            int e = ebase + s * 16;
            int r = __ldg(&row[e]);
            int c = __ldg(&col[e]);
            uint2 up = __ldg(&g_mh[r * HG + chg]);
            uint2 vp = __ldg(&g_aggh[c * HG + chg]);
            float2 ulo = __half22float2(*reinterpret_cast<__half2*>(&up.x));
            float2 uhi = __half22float2(*reinterpret_cast<__half2*>(&up.y));
            float2 vlo = __half22float2(*reinterpret_cast<__half2*>(&vp.x));
            float2 vhi = __half22float2(*reinterpret_cast<__half2*>(&vp.y));
            float4 a0 = __ldg(&a4[e * 4 + 0]);
            float4 a1 = __ldg(&a4[e * 4 + 1]);
            float4 a2 = __ldg(&a4[e * 4 + 2]);
            float4 a3 = __ldg(&a4[e * 4 + 3]);
            __half2 accl = __float2half2_rn(0.f);
            __half2 acch = __float2half2_rn(0.f);
            float av[16] = {a0.x, a0.y, a0.z, a0.w, a1.x, a1.y, a1.z, a1.w,
                            a2.x, a2.y, a2.z, a2.w, a3.x, a3.y, a3.z, a3.w};
#pragma unroll
            for (int k = 0; k < 16; k++) {
                __half2 ah = __float2half2_rn(av[k]);
                accl = __hfma2(ah, c3l[k], accl);
                acch = __hfma2(ah, c3h[k], acch);
            }
            float2 fl = __half22float2(accl);
            float2 fh = __half22float2(acch);
            float4 z;
            z.x = ulo.x + vlo.x + bz.x + fl.x;
            z.y = ulo.y + vlo.y + bz.y + fl.y;
            z.z = uhi.x + vhi.x + bz.z + fh.x;
            z.w = uhi.y + vhi.y + bz.w + fh.y;
            shp[s][tid] = tanh_fast(z.x) * wv.x + tanh_fast(z.y) * wv.y +
                          tanh_fast(z.z) * wv.z + tanh_fast(z.w) * wv.w;
        }
        __syncthreads();
        if (tid < 64) {
            int sSel = tid >> 4, e_l = tid & 15;
            float ss = 0.f;
#pragma unroll
            for (int jj = 0; jj < HG; jj++) ss += shp[sSel][e_l * HG + jj];
            out[rd * 64 + tid] = ss + bout;
        }
        __syncthreads();
    }
}

// ---------------- launch ----------------
extern "C" void kernel_launch(void* const* d_in, const int* in_sizes, int n_in,
                              void* d_out, int out_size) {
    const float* x     = (const float*)d_in[0];
    const int*   ei    = (const int*)d_in[1];
    const float* attr  = (const float*)d_in[2];
    const float* nlw   = (const float*)d_in[3];
    const float* nlb   = (const float*)d_in[4];
    const float* convw = (const float*)d_in[5];
    const float* convv = (const float*)d_in[6];
    const float* convb = (const float*)d_in[7];
    const float* gamma = (const float*)d_in[8];
    const float* beta  = (const float*)d_in[9];
    const float* W1    = (const float*)d_in[10];
    const float* b1    = (const float*)d_in[11];
    const float* W2    = (const float*)d_in[12];
    const float* b2e   = (const float*)d_in[13];
    const float* M1    = (const float*)d_in[14];
    const float* bm    = (const float*)d_in[15];
    const float* w2    = (const float*)d_in[16];
    const float* b2m   = (const float*)d_in[17];
    const int* row = ei;
    const int* col = ei + NE;
    float* out = (float*)d_out;

    float*  pC = nullptr;
    float*  pStats = nullptr;
    __half* pWt = nullptr;
    float*  pBias = nullptr;
    cudaGetSymbolAddress((void**)&pC, g_C);
    cudaGetSymbolAddress((void**)&pStats, g_statsL);
    cudaGetSymbolAddress((void**)&pWt, g_wt);
    cudaGetSymbolAddress((void**)&pBias, g_biasF);

    const int GBN = (NN + 95) / 96;    // 521 (node_lin)
    const int GBT = NNP / 128;         // 391 (tc gemm)

    k_prep<<<1, 160>>>(convw, convv, convb, nullptr, nullptr, nullptr,     // 0
                       pWt, pBias);
    k_node_lin<<<GBN, 288>>>(x, nlw, nlb);                                 // 1
    k_zero<<<(NN + 255) / 256, 256>>>();                                   // 2
    k_dualgemm_tc<<<GBT, 256>>>(pWt, pBias, 0);                            // 3 (profiled)
    k_deg<<<(NE + 255) / 256, 256>>>(col);                                 // 4
    k_scan<<<1, 1024>>>();                                                 // 5
    k_sort<<<(NE + 255) / 256, 256>>>(row, col);                           // 6
    k_aggregate<<<3125, dim3(HG, 16)>>>(pStats);                           // 7
    for (int t = 1; t < NLAY; t++) {
        k_prep<<<1, 160>>>(convw + t * HID * HID, convv + t * HID * HID,
                           convb + t * HID,
                           gamma + (t - 1) * HID, beta + (t - 1) * HID,
                           pStats + (t - 1) * 2 * HID,
                           pWt + t * 144 * 80, pBias + t * 144);
        k_dualgemm_tc<<<GBT, 256>>>(pWt + t * 144 * 80, pBias + t * 144, 0);
        k_aggregate<<<3125, dim3(HG, 16)>>>(pStats + t * 2 * HID);
    }
    k_fold<<<10, 288>>>(W1, W2, M1, b1, b2e, bm);
    k_prep<<<1, 160>>>(pC, pC + HID * HID, nullptr,
                       gamma + (NLAY - 1) * HID, beta + (NLAY - 1) * HID,
                       pStats + (NLAY - 1) * 2 * HID,
                       pWt + 3 * 144 * 80, pBias + 3 * 144);
    k_dualgemm_tc<<<GBT, 256>>>(pWt + 3 * 144 * 80, pBias + 3 * 144, 1);
    k_edge<<<1850, 288>>>(row, col, attr, w2, b2m, out);
}